// round 14
// baseline (speedup 1.0000x reference)
#include <cuda_runtime.h>
#include <math.h>

#define HID    16
#define HID2   8
#define BN_EPS 1e-5f

#define N_MAX   1048576
#define E_MAX   8388608
#define NB_MAX  4096
#define POOL_CAP (3 * 4194304)

// ---------------- scratch (device-side access only; never passed from host) ----------------
__device__ float4   g_pre [N_MAX * 4];
__device__ float4   g_h0  [N_MAX * 4];
__device__ float4   g_h1  [N_MAX * 4];
__device__ float4   g_h2  [N_MAX * 2];
__device__ int      g_cnt [N_MAX];
__device__ int      g_rowptr[N_MAX];
__device__ int      g_woff[N_MAX];
__device__ int      g_bsum[NB_MAX];
__device__ int      g_bpre[NB_MAX];
__device__ int      g_adj [E_MAX];
__device__ float    g_ssum[3][HID];
__device__ float    g_ssq [3][HID];
__device__ unsigned g_pool[POOL_CAP];

// ---------------- helpers ----------------
__device__ __forceinline__ float gelu_exact(float v) {
    return 0.5f * v * (1.0f + erff(v * 0.7071067811865476f));
}
__device__ __forceinline__ unsigned enc_f(float f) {
    unsigned u = __float_as_uint(f);
    return (u & 0x80000000u) ? ~u : (u | 0x80000000u);
}
__device__ __forceinline__ float dec_f(unsigned u) {
    return (u & 0x80000000u) ? __uint_as_float(u & 0x7FFFFFFFu)
                             : __uint_as_float(~u);
}
__device__ __forceinline__ unsigned long long pack2(float lo, float hi) {
    unsigned long long r;
    asm("mov.b64 %0, {%1, %2};" : "=l"(r) : "f"(lo), "f"(hi));
    return r;
}
__device__ __forceinline__ void unpack2(unsigned long long v, float& lo, float& hi) {
    asm("mov.b64 {%0, %1}, %2;" : "=f"(lo), "=f"(hi) : "l"(v));
}
__device__ __forceinline__ void ffma2(unsigned long long& d,
                                      unsigned long long a, unsigned long long b) {
    asm("fma.rn.f32x2 %0, %1, %2, %0;" : "+l"(d) : "l"(a), "l"(b));
}

__device__ __forceinline__ void bn_coef(int layer, int Cc, const float* gam,
                                        const float* bet, int N, float* sS, float* sT) {
    int tid = threadIdx.x;
    if (tid < Cc) {
        float inv = 1.0f / (float)N;
        float m   = g_ssum[layer][tid] * inv;
        float var = g_ssq[layer][tid] * inv - m * m;
        float sc  = gam[tid] * rsqrtf(var + BN_EPS);
        sS[tid] = sc;
        sT[tid] = bet[tid] - m * sc;
    }
}

template <int C>
__device__ __forceinline__ void warp_stats(const float* acc, int layer) {
#pragma unroll
    for (int j = 0; j < C; j++) {
        float v = acc[j];
        float q = v * v;
#pragma unroll
        for (int o = 16; o > 0; o >>= 1) {
            v += __shfl_xor_sync(0xffffffffu, v, o);
            q += __shfl_xor_sync(0xffffffffu, q, o);
        }
        if ((threadIdx.x & 31) == 0) {
            atomicAdd(&g_ssum[layer][j], v);
            atomicAdd(&g_ssq[layer][j],  q);
        }
    }
}

// ---------------- init ----------------
__global__ void k_init(int pool_n, int N) {
    int i = blockIdx.x * blockDim.x + threadIdx.x;
    if (i < 3 * HID) { ((float*)g_ssum)[i] = 0.f; ((float*)g_ssq)[i] = 0.f; }
    if (i < pool_n) g_pool[i] = 0u;
    if (i < N) g_cnt[i] = 0;
}

// ---------------- layer 0 GEMM (R9-proven): smem-staged x, fused stats ----------------
__global__ __launch_bounds__(256) void k_gemm0(const float* __restrict__ x,
                                               const float* __restrict__ W0,
                                               const float* __restrict__ b0,
                                               int N, int F) {
    extern __shared__ float xs[];          // [256][36]
    __shared__ float Wt[32 * HID];
    __shared__ float bs[HID];
    int tid = threadIdx.x;
    if (tid < HID) bs[tid] = b0[tid];

    int base = blockIdx.x * 256;
    int r = base + tid;
    bool act = r < N;

    unsigned long long accp[8];
#pragma unroll
    for (int q = 0; q < 8; q++) accp[q] = 0ull;

    int w  = tid >> 5;
    int l  = tid & 31;
    int lr = l >> 3;
    int lc = l & 7;
    int ntiles = F >> 5;

    for (int t = 0; t < ntiles; t++) {
        __syncthreads();
#pragma unroll
        for (int i = 0; i < 2; i++) {
            int idx = tid + i * 256;
            Wt[idx] = W0[(size_t)t * (32 * HID) + idx];
        }
#pragma unroll
        for (int k = 0; k < 8; k++) {
            int row_local = w * 32 + k * 4 + lr;
            int gr = base + row_local; if (gr >= N) gr = N - 1;
            float4 xv = __ldg((const float4*)(x + (size_t)gr * F + t * 32) + lc);
            *(float4*)&xs[row_local * 36 + lc * 4] = xv;
        }
        __syncthreads();
        const float* xr = &xs[tid * 36];
#pragma unroll
        for (int c4 = 0; c4 < 8; c4++) {
            float4 xv = *(const float4*)(xr + c4 * 4);
#pragma unroll
            for (int u = 0; u < 4; u++) {
                float xsc = (&xv.x)[u];
                unsigned long long xx = pack2(xsc, xsc);
                const ulonglong2* wr = (const ulonglong2*)&Wt[(c4 * 4 + u) * HID];
                ulonglong2 wa = wr[0], wb = wr[1];
                ffma2(accp[0], xx, wa.x); ffma2(accp[1], xx, wa.y);
                ffma2(accp[2], xx, wb.x); ffma2(accp[3], xx, wb.y);
                wa = wr[2]; wb = wr[3];
                ffma2(accp[4], xx, wa.x); ffma2(accp[5], xx, wa.y);
                ffma2(accp[6], xx, wb.x); ffma2(accp[7], xx, wb.y);
            }
        }
    }

    float acc[HID];
#pragma unroll
    for (int q = 0; q < 8; q++) unpack2(accp[q], acc[2 * q], acc[2 * q + 1]);
    if (act) {
#pragma unroll
        for (int j = 0; j < HID; j++) acc[j] += bs[j];
        float4* pr = (float4*)&g_pre[(size_t)r * 4];
        pr[0] = make_float4(acc[0],  acc[1],  acc[2],  acc[3]);
        pr[1] = make_float4(acc[4],  acc[5],  acc[6],  acc[7]);
        pr[2] = make_float4(acc[8],  acc[9],  acc[10], acc[11]);
        pr[3] = make_float4(acc[12], acc[13], acc[14], acc[15]);
    } else {
#pragma unroll
        for (int j = 0; j < HID; j++) acc[j] = 0.f;
    }
    warp_stats<HID>(acc, 0);
}

// ---------------- BN kernels: coalesced (thread per float4) ----------------
__global__ void k_bn0(const float* __restrict__ gam, const float* __restrict__ bet, int N) {
    __shared__ float sS[HID], sT[HID];
    bn_coef(0, HID, gam, bet, N, sS, sT);
    __syncthreads();
    int i = blockIdx.x * blockDim.x + threadIdx.x;
    if (i >= N * 4) return;
    int q = i & 3;
    float4 v = g_pre[i]; float4 r;
    r.x = gelu_exact(v.x * sS[q*4+0] + sT[q*4+0]);
    r.y = gelu_exact(v.y * sS[q*4+1] + sT[q*4+1]);
    r.z = gelu_exact(v.z * sS[q*4+2] + sT[q*4+2]);
    r.w = gelu_exact(v.w * sS[q*4+3] + sT[q*4+3]);
    g_h0[i] = r;
}

__global__ void k_bn1(const float* __restrict__ gam, const float* __restrict__ bet, int N) {
    __shared__ float sS[HID], sT[HID];
    bn_coef(1, HID, gam, bet, N, sS, sT);
    __syncthreads();
    int i = blockIdx.x * blockDim.x + threadIdx.x;
    if (i >= N * 4) return;
    int q = i & 3;
    float4 v = g_pre[i]; float4 r;
    r.x = v.x * sS[q*4+0] + sT[q*4+0];
    r.y = v.y * sS[q*4+1] + sT[q*4+1];
    r.z = v.z * sS[q*4+2] + sT[q*4+2];
    r.w = v.w * sS[q*4+3] + sT[q*4+3];
    g_h1[i] = r;
}

__global__ void k_bn2(const float* __restrict__ gam, const float* __restrict__ bet,
                      float4* __restrict__ outH, int N) {
    __shared__ float sS[HID2], sT[HID2];
    bn_coef(2, HID2, gam, bet, N, sS, sT);
    __syncthreads();
    int i = blockIdx.x * blockDim.x + threadIdx.x;
    if (i >= N * 2) return;
    int q = i & 1;
    float4 v = g_pre[i]; float4 r;      // layer-2 pre stored at stride 2
    r.x = v.x * sS[q*4+0] + sT[q*4+0];
    r.y = v.y * sS[q*4+1] + sT[q*4+1];
    r.z = v.z * sS[q*4+2] + sT[q*4+2];
    r.w = v.w * sS[q*4+3] + sT[q*4+3];
    g_h2[i] = r;
    if (outH) outH[i] = r;
}

// ---------------- CSR build ----------------
__global__ void k_hist(const int* __restrict__ ei, int N, int E) {
    int e = blockIdx.x * blockDim.x + threadIdx.x;
    if (e >= E) return;
    int d = __ldg(ei + E + e);
    if ((unsigned)d < (unsigned)N) atomicAdd(&g_cnt[d], 1);
}

#define SCAN_BS 256
__global__ void k_scan1(int n) {
    __shared__ int sh[SCAN_BS];
    int i = blockIdx.x * SCAN_BS + threadIdx.x;
    int v = (i < n) ? g_cnt[i] : 0;
    sh[threadIdx.x] = v;
    __syncthreads();
#pragma unroll
    for (int o = 1; o < SCAN_BS; o <<= 1) {
        int t = (threadIdx.x >= o) ? sh[threadIdx.x - o] : 0;
        __syncthreads();
        sh[threadIdx.x] += t;
        __syncthreads();
    }
    if (i < n) g_rowptr[i] = sh[threadIdx.x] - v;
    if (threadIdx.x == SCAN_BS - 1) g_bsum[blockIdx.x] = sh[threadIdx.x];
}

__global__ void k_scan2(int nb) {
    __shared__ int sh[1024];
    __shared__ int carry;
    if (threadIdx.x == 0) carry = 0;
    __syncthreads();
    for (int base = 0; base < nb; base += 1024) {
        int i = base + threadIdx.x;
        int v = (i < nb) ? g_bsum[i] : 0;
        sh[threadIdx.x] = v;
        __syncthreads();
        for (int o = 1; o < 1024; o <<= 1) {
            int t = (threadIdx.x >= o) ? sh[threadIdx.x - o] : 0;
            __syncthreads();
            sh[threadIdx.x] += t;
            __syncthreads();
        }
        if (i < nb) g_bpre[i] = sh[threadIdx.x] - v + carry;
        __syncthreads();
        if (threadIdx.x == 1023) carry += sh[1023];
        __syncthreads();
    }
}

__global__ void k_scan3(int n) {
    int i = blockIdx.x * SCAN_BS + threadIdx.x;
    if (i >= n) return;
    int v = g_rowptr[i] + g_bpre[blockIdx.x];
    g_rowptr[i] = v;
    g_woff[i]   = v;
}

__global__ void k_fill(const int* __restrict__ ei, int N, int E) {
    int e = blockIdx.x * blockDim.x + threadIdx.x;
    if (e >= E) return;
    int s = __ldg(ei + e);
    int d = __ldg(ei + E + e);
    if ((unsigned)s >= (unsigned)N || (unsigned)d >= (unsigned)N) return;
    int pos = atomicAdd(&g_woff[d], 1);
    if (pos < E_MAX) g_adj[pos] = s;
}

// ---------------- GIN: 4-lane cooperative gather (4x fewer L1tex wavefronts) ----------------
template <int C>
__global__ __launch_bounds__(256) void k_gin(const float* __restrict__ W,
                                             const float* __restrict__ b,
                                             int out_layer, int N) {
    const float4* hin  = (C == HID) ? g_h0 : g_h1;   // device-side selection ONLY
    float4*       hout = g_pre;

    __shared__ float Wsh[HID * C];
    __shared__ float bs[C];
    int tid = threadIdx.x;
    for (int i = tid; i < HID * C; i += 256) Wsh[i] = W[i];
    if (tid < C) bs[tid] = b[tid];
    __syncthreads();

    int q  = tid & 3;          // quarter of the 16-float row
    int nl = tid >> 2;         // local node 0..63
    int n  = blockIdx.x * 64 + nl;
    bool act = n < N;

    float4 t = make_float4(0.f, 0.f, 0.f, 0.f);
    if (act) {
        t = hin[(size_t)n * 4 + q];
        int p = g_rowptr[n], end = g_woff[n];
        for (; p + 3 < end; p += 4) {
            int s0 = __ldg(g_adj + p),     s1 = __ldg(g_adj + p + 1);
            int s2 = __ldg(g_adj + p + 2), s3 = __ldg(g_adj + p + 3);
            float4 a = hin[(size_t)s0 * 4 + q], bb = hin[(size_t)s1 * 4 + q];
            float4 c = hin[(size_t)s2 * 4 + q], d  = hin[(size_t)s3 * 4 + q];
            t.x += (a.x + bb.x) + (c.x + d.x);
            t.y += (a.y + bb.y) + (c.y + d.y);
            t.z += (a.z + bb.z) + (c.z + d.z);
            t.w += (a.w + bb.w) + (c.w + d.w);
        }
        for (; p < end; p++) {
            int s0 = __ldg(g_adj + p);
            float4 a = hin[(size_t)s0 * 4 + q];
            t.x += a.x; t.y += a.y; t.z += a.z; t.w += a.w;
        }
    }

    float tv[4] = { t.x, t.y, t.z, t.w };
    float acc[C];
#pragma unroll
    for (int j = 0; j < C; j++) acc[j] = 0.f;
#pragma unroll
    for (int k = 0; k < 4; k++) {
        float v = tv[k];
#pragma unroll
        for (int j = 0; j < C; j++) acc[j] += v * Wsh[(q * 4 + k) * C + j];
    }
#pragma unroll
    for (int j = 0; j < C; j++) {        // 4-lane butterfly reduce, then bias
        acc[j] += __shfl_xor_sync(0xffffffffu, acc[j], 1);
        acc[j] += __shfl_xor_sync(0xffffffffu, acc[j], 2);
        acc[j] += bs[j];
    }
    // store: match R9 layout — layer1 (C=16) stride 4; layer2 (C=8) stride 2
    if (act && q < C / 4) {
        hout[(size_t)n * (C / 4) + q] =
            make_float4(acc[q*4+0], acc[q*4+1], acc[q*4+2], acc[q*4+3]);
    }
    // stats: exactly one lane per node contributes
    bool contrib = act && (q == 0);
#pragma unroll
    for (int j = 0; j < C; j++) {
        float v = contrib ? acc[j] : 0.f;
        float qq = v * v;
#pragma unroll
        for (int o = 16; o > 0; o >>= 1) {
            v  += __shfl_xor_sync(0xffffffffu, v, o);
            qq += __shfl_xor_sync(0xffffffffu, qq, o);
        }
        if ((tid & 31) == 0) {
            atomicAdd(&g_ssum[out_layer][j], v);
            atomicAdd(&g_ssq[out_layer][j],  qq);
        }
    }
}

// ---------------- fused z0/z1/z2 (f32x2) + Z_sum + 3x segment_max ----------------
#define CHB 256
#define STR 260
#define ZTH 256
__global__ __launch_bounds__(ZTH) void k_bigz(const float* __restrict__ Wl0, const float* __restrict__ bl0,
                                              const float* __restrict__ Wl1, const float* __restrict__ bl1,
                                              const float* __restrict__ Wl2, const float* __restrict__ bl2,
                                              const int*   __restrict__ batch,
                                              float* __restrict__ Zs,
                                              int N, int DT, int NG) {
    __shared__ __align__(16) float sh[40 * STR];
    __shared__ int shb[CHB];
    int tid = threadIdx.x;
    int j = blockIdx.y * ZTH + tid;
    bool fj = j < DT;

    unsigned long long W0p[HID], W1p[HID], W2p[HID2];
    unsigned long long bb0p = 0, bb1p = 0, bb2p = 0;
    if (fj) {
#pragma unroll
        for (int k = 0; k < HID; k++) {
            float w = Wl0[k * DT + j]; W0p[k] = pack2(w, w);
            float v = Wl1[k * DT + j]; W1p[k] = pack2(v, v);
        }
#pragma unroll
        for (int k = 0; k < HID2; k++) { float w = Wl2[k * DT + j]; W2p[k] = pack2(w, w); }
        float t0 = bl0[j], t1 = bl1[j], t2 = bl2[j];
        bb0p = pack2(t0, t0); bb1p = pack2(t1, t1); bb2p = pack2(t2, t2);
    }

    int n0 = blockIdx.x * CHB;
    int valid = N - n0; if (valid > CHB) valid = CHB;

    const float* h0f = (const float*)g_h0;
    const float* h1f = (const float*)g_h1;
    const float* h2f = (const float*)g_h2;
    for (int idx = tid; idx < valid * 16; idx += ZTH) {
        int n = idx >> 4, k = idx & 15;
        sh[k * STR + n]        = h0f[(size_t)(n0 + n) * 16 + k];
        sh[(16 + k) * STR + n] = h1f[(size_t)(n0 + n) * 16 + k];
    }
    for (int idx = tid; idx < valid * 8; idx += ZTH) {
        int n = idx >> 3, k = idx & 7;
        sh[(32 + k) * STR + n] = h2f[(size_t)(n0 + n) * 8 + k];
    }
    if (tid < valid) shb[tid] = batch[n0 + tid];
    __syncthreads();
    if (!fj) return;

    const float NINF = __int_as_float(0xff800000);
    int cg = -1;
    float m0 = NINF, m1 = NINF, m2 = NINF;

    for (int nl = 0; nl < valid; nl += 4) {
        unsigned long long A0 = bb0p, B0 = bb0p;
        unsigned long long A1 = bb1p, B1 = bb1p;
        unsigned long long A2 = bb2p, B2 = bb2p;
#pragma unroll
        for (int k = 0; k < HID; k++) {
            ulonglong2 hv = *(const ulonglong2*)&sh[k * STR + nl];
            ffma2(A0, hv.x, W0p[k]); ffma2(B0, hv.y, W0p[k]);
        }
#pragma unroll
        for (int k = 0; k < HID; k++) {
            ulonglong2 hv = *(const ulonglong2*)&sh[(16 + k) * STR + nl];
            ffma2(A1, hv.x, W1p[k]); ffma2(B1, hv.y, W1p[k]);
        }
#pragma unroll
        for (int k = 0; k < HID2; k++) {
            ulonglong2 hv = *(const ulonglong2*)&sh[(32 + k) * STR + nl];
            ffma2(A2, hv.x, W2p[k]); ffma2(B2, hv.y, W2p[k]);
        }
        float a0[4], a1[4], a2[4];
        unpack2(A0, a0[0], a0[1]); unpack2(B0, a0[2], a0[3]);
        unpack2(A1, a1[0], a1[1]); unpack2(B1, a1[2], a1[3]);
        unpack2(A2, a2[0], a2[1]); unpack2(B2, a2[2], a2[3]);
#pragma unroll
        for (int i = 0; i < 4; i++) {
            if (nl + i >= valid) break;
            float z0 = gelu_exact(a0[i]);
            float z1 = a1[i], z2 = a2[i];
            if (Zs) Zs[(size_t)(n0 + nl + i) * DT + j] = z0 + z1 + z2;
            int g = shb[nl + i];
            if (g != cg) {
                if ((unsigned)cg < (unsigned)NG) {
                    atomicMax(&g_pool[(size_t)cg * DT + j],            enc_f(m0));
                    atomicMax(&g_pool[((size_t)NG + cg) * DT + j],     enc_f(m1));
                    atomicMax(&g_pool[((size_t)2 * NG + cg) * DT + j], enc_f(m2));
                }
                cg = g; m0 = NINF; m1 = NINF; m2 = NINF;
            }
            m0 = fmaxf(m0, z0); m1 = fmaxf(m1, z1); m2 = fmaxf(m2, z2);
        }
    }
    if ((unsigned)cg < (unsigned)NG) {
        atomicMax(&g_pool[(size_t)cg * DT + j],            enc_f(m0));
        atomicMax(&g_pool[((size_t)NG + cg) * DT + j],     enc_f(m1));
        atomicMax(&g_pool[((size_t)2 * NG + cg) * DT + j], enc_f(m2));
    }
}

// ---------------- pooled output ----------------
__global__ void k_out(float* __restrict__ out, int DT, int NG) {
    int g = blockIdx.x;
    for (int j = threadIdx.x; j < DT; j += blockDim.x) {
        out[(size_t)g * DT + j] = dec_f(g_pool[(size_t)g * DT + j])
                                + dec_f(g_pool[((size_t)NG + g) * DT + j])
                                + dec_f(g_pool[((size_t)2 * NG + g) * DT + j]);
    }
}

// ---------------- launch ----------------
extern "C" void kernel_launch(void* const* d_in, const int* in_sizes, int n_in,
                              void* d_out, int out_size) {
    const float* x   = (const float*)d_in[0];
    const int*   ei  = (const int*)  d_in[1];
    const int*   bat = (const int*)  d_in[2];
    const float* W0  = (const float*)d_in[3];
    const float* b0  = (const float*)d_in[4];
    const float* g0  = (const float*)d_in[5];
    const float* be0 = (const float*)d_in[6];
    const float* Wl0 = (const float*)d_in[7];
    const float* bl0 = (const float*)d_in[8];
    const float* W1  = (const float*)d_in[9];
    const float* b1  = (const float*)d_in[10];
    const float* g1  = (const float*)d_in[11];
    const float* be1 = (const float*)d_in[12];
    const float* Wl1 = (const float*)d_in[13];
    const float* bl1 = (const float*)d_in[14];
    const float* W2  = (const float*)d_in[15];
    const float* b2  = (const float*)d_in[16];
    const float* g2  = (const float*)d_in[17];
    const float* be2 = (const float*)d_in[18];
    const float* Wl2 = (const float*)d_in[19];
    const float* bl2 = (const float*)d_in[20];

    const int F  = in_sizes[3] / HID;
    int       N  = (F > 0) ? in_sizes[0] / F : 0;
    int       E  = in_sizes[1] / 2;
    const int DT = in_sizes[7] / HID;
    if (N > N_MAX) N = N_MAX;
    if (E > E_MAX) E = E_MAX;

    long long rem = (long long)out_size - (long long)N * DT - (long long)N * 8;
    int NG; bool full_layout;
    if (DT > 0 && rem > 0 && rem % DT == 0 && rem / DT <= 65536) {
        NG = (int)(rem / DT); full_layout = true;
    } else {
        NG = (DT > 0) ? out_size / DT : 0; full_layout = false;
    }
    long long pool_n = 3LL * NG * DT;
    if (pool_n > POOL_CAP) pool_n = POOL_CAP;

    float*  out  = (float*)d_out;
    float*  outZ = 0;
    float4* outH = 0;
    if (full_layout) {
        outZ = out + (size_t)NG * DT;
        outH = (float4*)(outZ + (size_t)N * DT);
    }

    const int nb   = (N + 255) / 256;
    const int nbg  = (N + 63) / 64;          // cooperative gin blocks
    const int nb4  = (N * 4 + 255) / 256;
    const int nb2  = (N * 2 + 255) / 256;
    const int nbe  = (E + 255) / 256;
    const int nsb  = (N + SCAN_BS - 1) / SCAN_BS;

    const size_t smem0 = 256 * 36 * sizeof(float);   // 36,864 B

    long long init_n = pool_n > N ? pool_n : N;
    k_init<<<((int)init_n + 255) / 256, 256>>>((int)pool_n, N);

    // launch idx 3 = gemm0 (ncu window target)
    k_hist<<<nbe, 256>>>(ei, N, E);
    k_scan1<<<nsb, SCAN_BS>>>(N);
    k_gemm0<<<nb, 256, smem0>>>(x, W0, b0, N, F);
    k_scan2<<<1, 1024>>>(nsb);
    k_scan3<<<nsb, SCAN_BS>>>(N);
    k_fill<<<nbe, 256>>>(ei, N, E);
    k_bn0<<<nb4, 256>>>(g0, be0, N);

    // layer 1: h0 -> pre1 -> h1 (cooperative gather)
    k_gin<HID><<<nbg, 256>>>(W1, b1, 1, N);
    k_bn1<<<nb4, 256>>>(g1, be1, N);

    // layer 2: h1 -> pre2 -> h2 (cooperative gather)
    k_gin<HID2><<<nbg, 256>>>(W2, b2, 2, N);
    k_bn2<<<nb2, 256>>>(g2, be2, outH, N);

    // fused projections + Z_sum + pools
    dim3 gz((N + CHB - 1) / CHB, (DT + ZTH - 1) / ZTH);
    k_bigz<<<gz, ZTH>>>(Wl0, bl0, Wl1, bl1, Wl2, bl2, bat, outZ, N, DT, NG);
    k_out<<<NG, (DT < 1024 ? DT : 1024)>>>(out, DT, NG);
}

// round 15
// speedup vs baseline: 1.5305x; 1.5305x over previous
#include <cuda_runtime.h>
#include <math.h>

#define HID    16
#define HID2   8
#define BN_EPS 1e-5f

#define N_MAX   1048576
#define E_MAX   8388608
#define NB_MAX  4096
#define POOL_CAP (3 * 4194304)

// ---------------- scratch (device-side access only; never passed from host) ----------------
__device__ float4   g_pre [N_MAX * 4];
__device__ float4   g_h0  [N_MAX * 4];
__device__ float4   g_h1  [N_MAX * 4];
__device__ float4   g_h2  [N_MAX * 2];
__device__ int      g_cnt [N_MAX];
__device__ int      g_rowptr[N_MAX];
__device__ int      g_woff[N_MAX];
__device__ int      g_bsum[NB_MAX];
__device__ int      g_bpre[NB_MAX];
__device__ int      g_adj [E_MAX];
__device__ float    g_ssum[3][HID];
__device__ float    g_ssq [3][HID];
__device__ unsigned g_pool[POOL_CAP];

// ---------------- helpers ----------------
__device__ __forceinline__ float gelu_exact(float v) {
    return 0.5f * v * (1.0f + erff(v * 0.7071067811865476f));
}
__device__ __forceinline__ unsigned enc_f(float f) {
    unsigned u = __float_as_uint(f);
    return (u & 0x80000000u) ? ~u : (u | 0x80000000u);
}
__device__ __forceinline__ float dec_f(unsigned u) {
    return (u & 0x80000000u) ? __uint_as_float(u & 0x7FFFFFFFu)
                             : __uint_as_float(~u);
}
__device__ __forceinline__ unsigned long long pack2(float lo, float hi) {
    unsigned long long r;
    asm("mov.b64 %0, {%1, %2};" : "=l"(r) : "f"(lo), "f"(hi));
    return r;
}
__device__ __forceinline__ void unpack2(unsigned long long v, float& lo, float& hi) {
    asm("mov.b64 {%0, %1}, %2;" : "=f"(lo), "=f"(hi) : "l"(v));
}
__device__ __forceinline__ void ffma2(unsigned long long& d,
                                      unsigned long long a, unsigned long long b) {
    asm("fma.rn.f32x2 %0, %1, %2, %0;" : "+l"(d) : "l"(a), "l"(b));
}

__device__ __forceinline__ void bn_coef(int layer, int Cc, const float* gam,
                                        const float* bet, int N, float* sS, float* sT) {
    int tid = threadIdx.x;
    if (tid < Cc) {
        float inv = 1.0f / (float)N;
        float m   = g_ssum[layer][tid] * inv;
        float var = g_ssq[layer][tid] * inv - m * m;
        float sc  = gam[tid] * rsqrtf(var + BN_EPS);
        sS[tid] = sc;
        sT[tid] = bet[tid] - m * sc;
    }
}

template <int C>
__device__ __forceinline__ void warp_stats(const float* acc, int layer) {
#pragma unroll
    for (int j = 0; j < C; j++) {
        float v = acc[j];
        float q = v * v;
#pragma unroll
        for (int o = 16; o > 0; o >>= 1) {
            v += __shfl_xor_sync(0xffffffffu, v, o);
            q += __shfl_xor_sync(0xffffffffu, q, o);
        }
        if ((threadIdx.x & 31) == 0) {
            atomicAdd(&g_ssum[layer][j], v);
            atomicAdd(&g_ssq[layer][j],  q);
        }
    }
}

// ---------------- init ----------------
__global__ void k_init(int pool_n, int N) {
    int i = blockIdx.x * blockDim.x + threadIdx.x;
    if (i < 3 * HID) { ((float*)g_ssum)[i] = 0.f; ((float*)g_ssq)[i] = 0.f; }
    if (i < pool_n) g_pool[i] = 0u;
    if (i < N) g_cnt[i] = 0;
}

// ---------------- layer 0 GEMM (R9-proven): smem-staged x, fused stats ----------------
__global__ __launch_bounds__(256) void k_gemm0(const float* __restrict__ x,
                                               const float* __restrict__ W0,
                                               const float* __restrict__ b0,
                                               int N, int F) {
    extern __shared__ float xs[];          // [256][36]
    __shared__ float Wt[32 * HID];
    __shared__ float bs[HID];
    int tid = threadIdx.x;
    if (tid < HID) bs[tid] = b0[tid];

    int base = blockIdx.x * 256;
    int r = base + tid;
    bool act = r < N;

    unsigned long long accp[8];
#pragma unroll
    for (int q = 0; q < 8; q++) accp[q] = 0ull;

    int w  = tid >> 5;
    int l  = tid & 31;
    int lr = l >> 3;
    int lc = l & 7;
    int ntiles = F >> 5;

    for (int t = 0; t < ntiles; t++) {
        __syncthreads();
#pragma unroll
        for (int i = 0; i < 2; i++) {
            int idx = tid + i * 256;
            Wt[idx] = W0[(size_t)t * (32 * HID) + idx];
        }
#pragma unroll
        for (int k = 0; k < 8; k++) {
            int row_local = w * 32 + k * 4 + lr;
            int gr = base + row_local; if (gr >= N) gr = N - 1;
            float4 xv = __ldg((const float4*)(x + (size_t)gr * F + t * 32) + lc);
            *(float4*)&xs[row_local * 36 + lc * 4] = xv;
        }
        __syncthreads();
        const float* xr = &xs[tid * 36];
#pragma unroll
        for (int c4 = 0; c4 < 8; c4++) {
            float4 xv = *(const float4*)(xr + c4 * 4);
#pragma unroll
            for (int u = 0; u < 4; u++) {
                float xsc = (&xv.x)[u];
                unsigned long long xx = pack2(xsc, xsc);
                const ulonglong2* wr = (const ulonglong2*)&Wt[(c4 * 4 + u) * HID];
                ulonglong2 wa = wr[0], wb = wr[1];
                ffma2(accp[0], xx, wa.x); ffma2(accp[1], xx, wa.y);
                ffma2(accp[2], xx, wb.x); ffma2(accp[3], xx, wb.y);
                wa = wr[2]; wb = wr[3];
                ffma2(accp[4], xx, wa.x); ffma2(accp[5], xx, wa.y);
                ffma2(accp[6], xx, wb.x); ffma2(accp[7], xx, wb.y);
            }
        }
    }

    float acc[HID];
#pragma unroll
    for (int q = 0; q < 8; q++) unpack2(accp[q], acc[2 * q], acc[2 * q + 1]);
    if (act) {
#pragma unroll
        for (int j = 0; j < HID; j++) acc[j] += bs[j];
        float4* pr = (float4*)&g_pre[(size_t)r * 4];
        pr[0] = make_float4(acc[0],  acc[1],  acc[2],  acc[3]);
        pr[1] = make_float4(acc[4],  acc[5],  acc[6],  acc[7]);
        pr[2] = make_float4(acc[8],  acc[9],  acc[10], acc[11]);
        pr[3] = make_float4(acc[12], acc[13], acc[14], acc[15]);
    } else {
#pragma unroll
        for (int j = 0; j < HID; j++) acc[j] = 0.f;
    }
    warp_stats<HID>(acc, 0);
}

// ---------------- BN kernels: coalesced (thread per float4) ----------------
__global__ void k_bn0(const float* __restrict__ gam, const float* __restrict__ bet, int N) {
    __shared__ float sS[HID], sT[HID];
    bn_coef(0, HID, gam, bet, N, sS, sT);
    __syncthreads();
    int i = blockIdx.x * blockDim.x + threadIdx.x;
    if (i >= N * 4) return;
    int q = i & 3;
    float4 v = g_pre[i]; float4 r;
    r.x = gelu_exact(v.x * sS[q*4+0] + sT[q*4+0]);
    r.y = gelu_exact(v.y * sS[q*4+1] + sT[q*4+1]);
    r.z = gelu_exact(v.z * sS[q*4+2] + sT[q*4+2]);
    r.w = gelu_exact(v.w * sS[q*4+3] + sT[q*4+3]);
    g_h0[i] = r;
}

__global__ void k_bn1(const float* __restrict__ gam, const float* __restrict__ bet, int N) {
    __shared__ float sS[HID], sT[HID];
    bn_coef(1, HID, gam, bet, N, sS, sT);
    __syncthreads();
    int i = blockIdx.x * blockDim.x + threadIdx.x;
    if (i >= N * 4) return;
    int q = i & 3;
    float4 v = g_pre[i]; float4 r;
    r.x = v.x * sS[q*4+0] + sT[q*4+0];
    r.y = v.y * sS[q*4+1] + sT[q*4+1];
    r.z = v.z * sS[q*4+2] + sT[q*4+2];
    r.w = v.w * sS[q*4+3] + sT[q*4+3];
    g_h1[i] = r;
}

__global__ void k_bn2(const float* __restrict__ gam, const float* __restrict__ bet,
                      float4* __restrict__ outH, int N) {
    __shared__ float sS[HID2], sT[HID2];
    bn_coef(2, HID2, gam, bet, N, sS, sT);
    __syncthreads();
    int i = blockIdx.x * blockDim.x + threadIdx.x;
    if (i >= N * 2) return;
    int q = i & 1;
    float4 v = g_pre[i]; float4 r;      // layer-2 pre stored at stride 2
    r.x = v.x * sS[q*4+0] + sT[q*4+0];
    r.y = v.y * sS[q*4+1] + sT[q*4+1];
    r.z = v.z * sS[q*4+2] + sT[q*4+2];
    r.w = v.w * sS[q*4+3] + sT[q*4+3];
    g_h2[i] = r;
    if (outH) __stcs(&outH[i], r);
}

// ---------------- CSR build ----------------
__global__ void k_hist(const int* __restrict__ ei, int N, int E) {
    int e = blockIdx.x * blockDim.x + threadIdx.x;
    if (e >= E) return;
    int d = __ldg(ei + E + e);
    if ((unsigned)d < (unsigned)N) atomicAdd(&g_cnt[d], 1);
}

#define SCAN_BS 256
__global__ void k_scan1(int n) {
    __shared__ int sh[SCAN_BS];
    int i = blockIdx.x * SCAN_BS + threadIdx.x;
    int v = (i < n) ? g_cnt[i] : 0;
    sh[threadIdx.x] = v;
    __syncthreads();
#pragma unroll
    for (int o = 1; o < SCAN_BS; o <<= 1) {
        int t = (threadIdx.x >= o) ? sh[threadIdx.x - o] : 0;
        __syncthreads();
        sh[threadIdx.x] += t;
        __syncthreads();
    }
    if (i < n) g_rowptr[i] = sh[threadIdx.x] - v;
    if (threadIdx.x == SCAN_BS - 1) g_bsum[blockIdx.x] = sh[threadIdx.x];
}

__global__ void k_scan2(int nb) {
    __shared__ int sh[1024];
    __shared__ int carry;
    if (threadIdx.x == 0) carry = 0;
    __syncthreads();
    for (int base = 0; base < nb; base += 1024) {
        int i = base + threadIdx.x;
        int v = (i < nb) ? g_bsum[i] : 0;
        sh[threadIdx.x] = v;
        __syncthreads();
        for (int o = 1; o < 1024; o <<= 1) {
            int t = (threadIdx.x >= o) ? sh[threadIdx.x - o] : 0;
            __syncthreads();
            sh[threadIdx.x] += t;
            __syncthreads();
        }
        if (i < nb) g_bpre[i] = sh[threadIdx.x] - v + carry;
        __syncthreads();
        if (threadIdx.x == 1023) carry += sh[1023];
        __syncthreads();
    }
}

__global__ void k_scan3(int n) {
    int i = blockIdx.x * SCAN_BS + threadIdx.x;
    if (i >= n) return;
    int v = g_rowptr[i] + g_bpre[blockIdx.x];
    g_rowptr[i] = v;
    g_woff[i]   = v;
}

__global__ void k_fill(const int* __restrict__ ei, int N, int E) {
    int e = blockIdx.x * blockDim.x + threadIdx.x;
    if (e >= E) return;
    int s = __ldg(ei + e);
    int d = __ldg(ei + E + e);
    if ((unsigned)s >= (unsigned)N || (unsigned)d >= (unsigned)N) return;
    int pos = atomicAdd(&g_woff[d], 1);
    if (pos < E_MAX) g_adj[pos] = s;
}

// ---------------- GIN (per-thread, R9-proven): gather + GEMM + stats ----------------
template <int C>
__global__ __launch_bounds__(256) void k_gin(const float* __restrict__ W,
                                             const float* __restrict__ b,
                                             int out_layer, int N) {
    const float4* hin = (C == HID) ? g_h0 : g_h1;   // device-side selection ONLY

    __shared__ float Wsh[HID * C];
    __shared__ float bs[C];
    int tid = threadIdx.x;
    for (int i = tid; i < HID * C; i += 256) Wsh[i] = W[i];
    if (tid < C) bs[tid] = b[tid];
    __syncthreads();

    int n = blockIdx.x * 256 + tid;
    bool act = n < N;
    float acc[C];
#pragma unroll
    for (int j = 0; j < C; j++) acc[j] = 0.f;

    if (act) {
        float4 t0 = hin[(size_t)n * 4 + 0];
        float4 t1 = hin[(size_t)n * 4 + 1];
        float4 t2 = hin[(size_t)n * 4 + 2];
        float4 t3 = hin[(size_t)n * 4 + 3];

        int p   = g_rowptr[n];
        int end = g_woff[n];
        for (; p + 1 < end; p += 2) {
            int s0 = __ldg(g_adj + p);
            int s1 = __ldg(g_adj + p + 1);
            float4 a0 = hin[(size_t)s0 * 4 + 0], b0v = hin[(size_t)s1 * 4 + 0];
            float4 a1 = hin[(size_t)s0 * 4 + 1], b1v = hin[(size_t)s1 * 4 + 1];
            float4 a2 = hin[(size_t)s0 * 4 + 2], b2v = hin[(size_t)s1 * 4 + 2];
            float4 a3 = hin[(size_t)s0 * 4 + 3], b3v = hin[(size_t)s1 * 4 + 3];
            t0.x += a0.x + b0v.x; t0.y += a0.y + b0v.y; t0.z += a0.z + b0v.z; t0.w += a0.w + b0v.w;
            t1.x += a1.x + b1v.x; t1.y += a1.y + b1v.y; t1.z += a1.z + b1v.z; t1.w += a1.w + b1v.w;
            t2.x += a2.x + b2v.x; t2.y += a2.y + b2v.y; t2.z += a2.z + b2v.z; t2.w += a2.w + b2v.w;
            t3.x += a3.x + b3v.x; t3.y += a3.y + b3v.y; t3.z += a3.z + b3v.z; t3.w += a3.w + b3v.w;
        }
        if (p < end) {
            int s0 = __ldg(g_adj + p);
            float4 a0 = hin[(size_t)s0 * 4 + 0];
            float4 a1 = hin[(size_t)s0 * 4 + 1];
            float4 a2 = hin[(size_t)s0 * 4 + 2];
            float4 a3 = hin[(size_t)s0 * 4 + 3];
            t0.x += a0.x; t0.y += a0.y; t0.z += a0.z; t0.w += a0.w;
            t1.x += a1.x; t1.y += a1.y; t1.z += a1.z; t1.w += a1.w;
            t2.x += a2.x; t2.y += a2.y; t2.z += a2.z; t2.w += a2.w;
            t3.x += a3.x; t3.y += a3.y; t3.z += a3.z; t3.w += a3.w;
        }

        float t[HID] = { t0.x, t0.y, t0.z, t0.w, t1.x, t1.y, t1.z, t1.w,
                         t2.x, t2.y, t2.z, t2.w, t3.x, t3.y, t3.z, t3.w };
#pragma unroll
        for (int j = 0; j < C; j++) acc[j] = bs[j];
#pragma unroll
        for (int k = 0; k < HID; k++) {
            float tv = t[k];
#pragma unroll
            for (int j = 0; j < C; j++) acc[j] += tv * Wsh[k * C + j];
        }
#pragma unroll
        for (int q = 0; q < C / 4; q++) {
            g_pre[(size_t)n * (C / 4) + q] =
                make_float4(acc[q*4+0], acc[q*4+1], acc[q*4+2], acc[q*4+3]);
        }
    }
    warp_stats<C>(acc, out_layer);
}

// ---------------- fused z0/z1/z2 (f32x2) + Z_sum + 3x segment_max ----------------
#define CHB 256
#define STR 260
#define ZTH 256
__global__ __launch_bounds__(ZTH) void k_bigz(const float* __restrict__ Wl0, const float* __restrict__ bl0,
                                              const float* __restrict__ Wl1, const float* __restrict__ bl1,
                                              const float* __restrict__ Wl2, const float* __restrict__ bl2,
                                              const int*   __restrict__ batch,
                                              float* __restrict__ Zs,
                                              int N, int DT, int NG) {
    __shared__ __align__(16) float sh[40 * STR];
    __shared__ int shb[CHB];
    int tid = threadIdx.x;
    int j = blockIdx.y * ZTH + tid;
    bool fj = j < DT;

    unsigned long long W0p[HID], W1p[HID], W2p[HID2];
    unsigned long long bb0p = 0, bb1p = 0, bb2p = 0;
    if (fj) {
#pragma unroll
        for (int k = 0; k < HID; k++) {
            float w = Wl0[k * DT + j]; W0p[k] = pack2(w, w);
            float v = Wl1[k * DT + j]; W1p[k] = pack2(v, v);
        }
#pragma unroll
        for (int k = 0; k < HID2; k++) { float w = Wl2[k * DT + j]; W2p[k] = pack2(w, w); }
        float t0 = bl0[j], t1 = bl1[j], t2 = bl2[j];
        bb0p = pack2(t0, t0); bb1p = pack2(t1, t1); bb2p = pack2(t2, t2);
    }

    int n0 = blockIdx.x * CHB;
    int valid = N - n0; if (valid > CHB) valid = CHB;

    const float* h0f = (const float*)g_h0;
    const float* h1f = (const float*)g_h1;
    const float* h2f = (const float*)g_h2;
    for (int idx = tid; idx < valid * 16; idx += ZTH) {
        int n = idx >> 4, k = idx & 15;
        sh[k * STR + n]        = h0f[(size_t)(n0 + n) * 16 + k];
        sh[(16 + k) * STR + n] = h1f[(size_t)(n0 + n) * 16 + k];
    }
    for (int idx = tid; idx < valid * 8; idx += ZTH) {
        int n = idx >> 3, k = idx & 7;
        sh[(32 + k) * STR + n] = h2f[(size_t)(n0 + n) * 8 + k];
    }
    if (tid < valid) shb[tid] = batch[n0 + tid];
    __syncthreads();
    if (!fj) return;

    const float NINF = __int_as_float(0xff800000);
    int cg = -1;
    float m0 = NINF, m1 = NINF, m2 = NINF;

    for (int nl = 0; nl < valid; nl += 4) {
        unsigned long long A0 = bb0p, B0 = bb0p;
        unsigned long long A1 = bb1p, B1 = bb1p;
        unsigned long long A2 = bb2p, B2 = bb2p;
#pragma unroll
        for (int k = 0; k < HID; k++) {
            ulonglong2 hv = *(const ulonglong2*)&sh[k * STR + nl];
            ffma2(A0, hv.x, W0p[k]); ffma2(B0, hv.y, W0p[k]);
        }
#pragma unroll
        for (int k = 0; k < HID; k++) {
            ulonglong2 hv = *(const ulonglong2*)&sh[(16 + k) * STR + nl];
            ffma2(A1, hv.x, W1p[k]); ffma2(B1, hv.y, W1p[k]);
        }
#pragma unroll
        for (int k = 0; k < HID2; k++) {
            ulonglong2 hv = *(const ulonglong2*)&sh[(32 + k) * STR + nl];
            ffma2(A2, hv.x, W2p[k]); ffma2(B2, hv.y, W2p[k]);
        }
        float a0[4], a1[4], a2[4];
        unpack2(A0, a0[0], a0[1]); unpack2(B0, a0[2], a0[3]);
        unpack2(A1, a1[0], a1[1]); unpack2(B1, a1[2], a1[3]);
        unpack2(A2, a2[0], a2[1]); unpack2(B2, a2[2], a2[3]);
#pragma unroll
        for (int i = 0; i < 4; i++) {
            if (nl + i >= valid) break;
            float z0 = gelu_exact(a0[i]);
            float z1 = a1[i], z2 = a2[i];
            if (Zs) __stcs(&Zs[(size_t)(n0 + nl + i) * DT + j], z0 + z1 + z2);
            int g = shb[nl + i];
            if (g != cg) {
                if ((unsigned)cg < (unsigned)NG) {
                    atomicMax(&g_pool[(size_t)cg * DT + j],            enc_f(m0));
                    atomicMax(&g_pool[((size_t)NG + cg) * DT + j],     enc_f(m1));
                    atomicMax(&g_pool[((size_t)2 * NG + cg) * DT + j], enc_f(m2));
                }
                cg = g; m0 = NINF; m1 = NINF; m2 = NINF;
            }
            m0 = fmaxf(m0, z0); m1 = fmaxf(m1, z1); m2 = fmaxf(m2, z2);
        }
    }
    if ((unsigned)cg < (unsigned)NG) {
        atomicMax(&g_pool[(size_t)cg * DT + j],            enc_f(m0));
        atomicMax(&g_pool[((size_t)NG + cg) * DT + j],     enc_f(m1));
        atomicMax(&g_pool[((size_t)2 * NG + cg) * DT + j], enc_f(m2));
    }
}

// ---------------- pooled output ----------------
__global__ void k_out(float* __restrict__ out, int DT, int NG) {
    int g = blockIdx.x;
    for (int j = threadIdx.x; j < DT; j += blockDim.x) {
        out[(size_t)g * DT + j] = dec_f(g_pool[(size_t)g * DT + j])
                                + dec_f(g_pool[((size_t)NG + g) * DT + j])
                                + dec_f(g_pool[((size_t)2 * NG + g) * DT + j]);
    }
}

// ---------------- launch ----------------
extern "C" void kernel_launch(void* const* d_in, const int* in_sizes, int n_in,
                              void* d_out, int out_size) {
    const float* x   = (const float*)d_in[0];
    const int*   ei  = (const int*)  d_in[1];
    const int*   bat = (const int*)  d_in[2];
    const float* W0  = (const float*)d_in[3];
    const float* b0  = (const float*)d_in[4];
    const float* g0  = (const float*)d_in[5];
    const float* be0 = (const float*)d_in[6];
    const float* Wl0 = (const float*)d_in[7];
    const float* bl0 = (const float*)d_in[8];
    const float* W1  = (const float*)d_in[9];
    const float* b1  = (const float*)d_in[10];
    const float* g1  = (const float*)d_in[11];
    const float* be1 = (const float*)d_in[12];
    const float* Wl1 = (const float*)d_in[13];
    const float* bl1 = (const float*)d_in[14];
    const float* W2  = (const float*)d_in[15];
    const float* b2  = (const float*)d_in[16];
    const float* g2  = (const float*)d_in[17];
    const float* be2 = (const float*)d_in[18];
    const float* Wl2 = (const float*)d_in[19];
    const float* bl2 = (const float*)d_in[20];

    const int F  = in_sizes[3] / HID;
    int       N  = (F > 0) ? in_sizes[0] / F : 0;
    int       E  = in_sizes[1] / 2;
    const int DT = in_sizes[7] / HID;
    if (N > N_MAX) N = N_MAX;
    if (E > E_MAX) E = E_MAX;

    long long rem = (long long)out_size - (long long)N * DT - (long long)N * 8;
    int NG; bool full_layout;
    if (DT > 0 && rem > 0 && rem % DT == 0 && rem / DT <= 65536) {
        NG = (int)(rem / DT); full_layout = true;
    } else {
        NG = (DT > 0) ? out_size / DT : 0; full_layout = false;
    }
    long long pool_n = 3LL * NG * DT;
    if (pool_n > POOL_CAP) pool_n = POOL_CAP;

    float*  out  = (float*)d_out;
    float*  outZ = 0;
    float4* outH = 0;
    if (full_layout) {
        outZ = out + (size_t)NG * DT;
        outH = (float4*)(outZ + (size_t)N * DT);
    }

    const int nb   = (N + 255) / 256;
    const int nb4  = (N * 4 + 255) / 256;
    const int nb2  = (N * 2 + 255) / 256;
    const int nbe  = (E + 255) / 256;
    const int nsb  = (N + SCAN_BS - 1) / SCAN_BS;

    const size_t smem0 = 256 * 36 * sizeof(float);   // 36,864 B

    long long init_n = pool_n > N ? pool_n : N;
    k_init<<<((int)init_n + 255) / 256, 256>>>((int)pool_n, N);

    // launch idx 3 = gemm0 (ncu window target)
    k_hist<<<nbe, 256>>>(ei, N, E);
    k_scan1<<<nsb, SCAN_BS>>>(N);
    k_gemm0<<<nb, 256, smem0>>>(x, W0, b0, N, F);
    k_scan2<<<1, 1024>>>(nsb);
    k_scan3<<<nsb, SCAN_BS>>>(N);
    k_fill<<<nbe, 256>>>(ei, N, E);
    k_bn0<<<nb4, 256>>>(g0, be0, N);

    // layer 1: h0 -> pre1 -> h1
    k_gin<HID><<<nb, 256>>>(W1, b1, 1, N);
    k_bn1<<<nb4, 256>>>(g1, be1, N);

    // layer 2: h1 -> pre2 -> h2
    k_gin<HID2><<<nb, 256>>>(W2, b2, 2, N);
    k_bn2<<<nb2, 256>>>(g2, be2, outH, N);

    // fused projections + Z_sum + pools
    dim3 gz((N + CHB - 1) / CHB, (DT + ZTH - 1) / ZTH);
    k_bigz<<<gz, ZTH>>>(Wl0, bl0, Wl1, bl1, Wl2, bl2, bat, outZ, N, DT, NG);
    k_out<<<NG, (DT < 1024 ? DT : 1024)>>>(out, DT, NG);
}

// round 16
// speedup vs baseline: 1.5314x; 1.0006x over previous
#include <cuda_runtime.h>
#include <math.h>

#define HID    16
#define HID2   8
#define BN_EPS 1e-5f

#define N_MAX   1048576
#define E_MAX   8388608
#define NB_MAX  4096
#define POOL_CAP (3 * 4194304)

// ---------------- scratch (device-side access only; never passed from host) ----------------
__device__ float4   g_pre [N_MAX * 4];   // pre1 (kept live through bigz)
__device__ float4   g_h0  [N_MAX * 4];
__device__ float4   g_h1  [N_MAX * 4];   // repurposed: pre2 (stride 2) after gin<8>
__device__ float4   g_h2  [N_MAX * 2];
__device__ int      g_cnt [N_MAX];
__device__ int      g_rowptr[N_MAX];
__device__ int      g_woff[N_MAX];
__device__ int      g_bsum[NB_MAX];
__device__ int      g_bpre[NB_MAX];
__device__ int      g_adj [E_MAX];
__device__ float    g_ssum[3][HID];
__device__ float    g_ssq [3][HID];
__device__ unsigned g_pool[POOL_CAP];

// ---------------- helpers ----------------
__device__ __forceinline__ float gelu_exact(float v) {
    return 0.5f * v * (1.0f + erff(v * 0.7071067811865476f));
}
__device__ __forceinline__ unsigned enc_f(float f) {
    unsigned u = __float_as_uint(f);
    return (u & 0x80000000u) ? ~u : (u | 0x80000000u);
}
__device__ __forceinline__ float dec_f(unsigned u) {
    return (u & 0x80000000u) ? __uint_as_float(u & 0x7FFFFFFFu)
                             : __uint_as_float(~u);
}
__device__ __forceinline__ unsigned long long pack2(float lo, float hi) {
    unsigned long long r;
    asm("mov.b64 %0, {%1, %2};" : "=l"(r) : "f"(lo), "f"(hi));
    return r;
}
__device__ __forceinline__ void unpack2(unsigned long long v, float& lo, float& hi) {
    asm("mov.b64 {%0, %1}, %2;" : "=f"(lo), "=f"(hi) : "l"(v));
}
__device__ __forceinline__ void ffma2(unsigned long long& d,
                                      unsigned long long a, unsigned long long b) {
    asm("fma.rn.f32x2 %0, %1, %2, %0;" : "+l"(d) : "l"(a), "l"(b));
}

__device__ __forceinline__ void bn_coef(int layer, int Cc, const float* gam,
                                        const float* bet, int N, float* sS, float* sT) {
    int tid = threadIdx.x;
    if (tid < Cc) {
        float inv = 1.0f / (float)N;
        float m   = g_ssum[layer][tid] * inv;
        float var = g_ssq[layer][tid] * inv - m * m;
        float sc  = gam[tid] * rsqrtf(var + BN_EPS);
        sS[tid] = sc;
        sT[tid] = bet[tid] - m * sc;
    }
}

template <int C>
__device__ __forceinline__ void warp_stats(const float* acc, int layer) {
#pragma unroll
    for (int j = 0; j < C; j++) {
        float v = acc[j];
        float q = v * v;
#pragma unroll
        for (int o = 16; o > 0; o >>= 1) {
            v += __shfl_xor_sync(0xffffffffu, v, o);
            q += __shfl_xor_sync(0xffffffffu, q, o);
        }
        if ((threadIdx.x & 31) == 0) {
            atomicAdd(&g_ssum[layer][j], v);
            atomicAdd(&g_ssq[layer][j],  q);
        }
    }
}

// ---------------- init ----------------
__global__ void k_init(int pool_n, int N) {
    int i = blockIdx.x * blockDim.x + threadIdx.x;
    if (i < 3 * HID) { ((float*)g_ssum)[i] = 0.f; ((float*)g_ssq)[i] = 0.f; }
    if (i < pool_n) g_pool[i] = 0u;
    if (i < N) g_cnt[i] = 0;
}

// ---------------- layer 0 GEMM (R9-proven): smem-staged x, fused stats ----------------
__global__ __launch_bounds__(256) void k_gemm0(const float* __restrict__ x,
                                               const float* __restrict__ W0,
                                               const float* __restrict__ b0,
                                               int N, int F) {
    extern __shared__ float xs[];          // [256][36]
    __shared__ float Wt[32 * HID];
    __shared__ float bs[HID];
    int tid = threadIdx.x;
    if (tid < HID) bs[tid] = b0[tid];

    int base = blockIdx.x * 256;
    int r = base + tid;
    bool act = r < N;

    unsigned long long accp[8];
#pragma unroll
    for (int q = 0; q < 8; q++) accp[q] = 0ull;

    int w  = tid >> 5;
    int l  = tid & 31;
    int lr = l >> 3;
    int lc = l & 7;
    int ntiles = F >> 5;

    for (int t = 0; t < ntiles; t++) {
        __syncthreads();
#pragma unroll
        for (int i = 0; i < 2; i++) {
            int idx = tid + i * 256;
            Wt[idx] = W0[(size_t)t * (32 * HID) + idx];
        }
#pragma unroll
        for (int k = 0; k < 8; k++) {
            int row_local = w * 32 + k * 4 + lr;
            int gr = base + row_local; if (gr >= N) gr = N - 1;
            float4 xv = __ldg((const float4*)(x + (size_t)gr * F + t * 32) + lc);
            *(float4*)&xs[row_local * 36 + lc * 4] = xv;
        }
        __syncthreads();
        const float* xr = &xs[tid * 36];
#pragma unroll
        for (int c4 = 0; c4 < 8; c4++) {
            float4 xv = *(const float4*)(xr + c4 * 4);
#pragma unroll
            for (int u = 0; u < 4; u++) {
                float xsc = (&xv.x)[u];
                unsigned long long xx = pack2(xsc, xsc);
                const ulonglong2* wr = (const ulonglong2*)&Wt[(c4 * 4 + u) * HID];
                ulonglong2 wa = wr[0], wb = wr[1];
                ffma2(accp[0], xx, wa.x); ffma2(accp[1], xx, wa.y);
                ffma2(accp[2], xx, wb.x); ffma2(accp[3], xx, wb.y);
                wa = wr[2]; wb = wr[3];
                ffma2(accp[4], xx, wa.x); ffma2(accp[5], xx, wa.y);
                ffma2(accp[6], xx, wb.x); ffma2(accp[7], xx, wb.y);
            }
        }
    }

    float acc[HID];
#pragma unroll
    for (int q = 0; q < 8; q++) unpack2(accp[q], acc[2 * q], acc[2 * q + 1]);
    if (act) {
#pragma unroll
        for (int j = 0; j < HID; j++) acc[j] += bs[j];
        float4* pr = (float4*)&g_pre[(size_t)r * 4];
        pr[0] = make_float4(acc[0],  acc[1],  acc[2],  acc[3]);
        pr[1] = make_float4(acc[4],  acc[5],  acc[6],  acc[7]);
        pr[2] = make_float4(acc[8],  acc[9],  acc[10], acc[11]);
        pr[3] = make_float4(acc[12], acc[13], acc[14], acc[15]);
    } else {
#pragma unroll
        for (int j = 0; j < HID; j++) acc[j] = 0.f;
    }
    warp_stats<HID>(acc, 0);
}

// ---------------- BN kernels: coalesced (thread per float4) ----------------
__global__ void k_bn0(const float* __restrict__ gam, const float* __restrict__ bet, int N) {
    __shared__ float sS[HID], sT[HID];
    bn_coef(0, HID, gam, bet, N, sS, sT);
    __syncthreads();
    int i = blockIdx.x * blockDim.x + threadIdx.x;
    if (i >= N * 4) return;
    int q = i & 3;
    float4 v = g_pre[i]; float4 r;
    r.x = gelu_exact(v.x * sS[q*4+0] + sT[q*4+0]);
    r.y = gelu_exact(v.y * sS[q*4+1] + sT[q*4+1]);
    r.z = gelu_exact(v.z * sS[q*4+2] + sT[q*4+2]);
    r.w = gelu_exact(v.w * sS[q*4+3] + sT[q*4+3]);
    g_h0[i] = r;
}

__global__ void k_bn2(const float* __restrict__ gam, const float* __restrict__ bet,
                      float4* __restrict__ outH, int N) {
    __shared__ float sS[HID2], sT[HID2];
    bn_coef(2, HID2, gam, bet, N, sS, sT);
    __syncthreads();
    int i = blockIdx.x * blockDim.x + threadIdx.x;
    if (i >= N * 2) return;
    int q = i & 1;
    float4 v = g_h1[i]; float4 r;       // pre2 lives in g_h1 (stride 2)
    r.x = v.x * sS[q*4+0] + sT[q*4+0];
    r.y = v.y * sS[q*4+1] + sT[q*4+1];
    r.z = v.z * sS[q*4+2] + sT[q*4+2];
    r.w = v.w * sS[q*4+3] + sT[q*4+3];
    g_h2[i] = r;
    if (outH) __stcs(&outH[i], r);
}

// ---------------- CSR build ----------------
__global__ void k_hist(const int* __restrict__ ei, int N, int E) {
    int e = blockIdx.x * blockDim.x + threadIdx.x;
    if (e >= E) return;
    int d = __ldg(ei + E + e);
    if ((unsigned)d < (unsigned)N) atomicAdd(&g_cnt[d], 1);
}

#define SCAN_BS 256
__global__ void k_scan1(int n) {
    __shared__ int sh[SCAN_BS];
    int i = blockIdx.x * SCAN_BS + threadIdx.x;
    int v = (i < n) ? g_cnt[i] : 0;
    sh[threadIdx.x] = v;
    __syncthreads();
#pragma unroll
    for (int o = 1; o < SCAN_BS; o <<= 1) {
        int t = (threadIdx.x >= o) ? sh[threadIdx.x - o] : 0;
        __syncthreads();
        sh[threadIdx.x] += t;
        __syncthreads();
    }
    if (i < n) g_rowptr[i] = sh[threadIdx.x] - v;
    if (threadIdx.x == SCAN_BS - 1) g_bsum[blockIdx.x] = sh[threadIdx.x];
}

__global__ void k_scan2(int nb) {
    __shared__ int sh[1024];
    __shared__ int carry;
    if (threadIdx.x == 0) carry = 0;
    __syncthreads();
    for (int base = 0; base < nb; base += 1024) {
        int i = base + threadIdx.x;
        int v = (i < nb) ? g_bsum[i] : 0;
        sh[threadIdx.x] = v;
        __syncthreads();
        for (int o = 1; o < 1024; o <<= 1) {
            int t = (threadIdx.x >= o) ? sh[threadIdx.x - o] : 0;
            __syncthreads();
            sh[threadIdx.x] += t;
            __syncthreads();
        }
        if (i < nb) g_bpre[i] = sh[threadIdx.x] - v + carry;
        __syncthreads();
        if (threadIdx.x == 1023) carry += sh[1023];
        __syncthreads();
    }
}

__global__ void k_scan3(int n) {
    int i = blockIdx.x * SCAN_BS + threadIdx.x;
    if (i >= n) return;
    int v = g_rowptr[i] + g_bpre[blockIdx.x];
    g_rowptr[i] = v;
    g_woff[i]   = v;
}

__global__ void k_fill(const int* __restrict__ ei, int N, int E) {
    int e = blockIdx.x * blockDim.x + threadIdx.x;
    if (e >= E) return;
    int s = __ldg(ei + e);
    int d = __ldg(ei + E + e);
    if ((unsigned)s >= (unsigned)N || (unsigned)d >= (unsigned)N) return;
    int pos = atomicAdd(&g_woff[d], 1);
    if (pos < E_MAX) g_adj[pos] = s;
}

// ---------------- GIN (per-thread, R9-proven gather) + optional analytic BN1 ----------------
// AFF=false: in=g_h0 (h0),           out=g_pre (stride 4, pre1), stats layer 1
// AFF=true : in=g_pre (pre1+affine), out=g_h1  (stride 2, pre2), stats layer 2
template <int C, bool AFF>
__global__ __launch_bounds__(256) void k_gin(const float* __restrict__ W,
                                             const float* __restrict__ b,
                                             const float* __restrict__ gam_in,
                                             const float* __restrict__ bet_in,
                                             int out_layer, int N) {
    const float4* hin  = AFF ? g_pre : g_h0;   // device-side selection ONLY
    float4*       hout = AFF ? g_h1  : g_pre;

    __shared__ float Wsh[HID * C];
    __shared__ float bs[C];
    __shared__ float sS[HID], sT[HID];
    int tid = threadIdx.x;
    for (int i = tid; i < HID * C; i += 256) Wsh[i] = W[i];
    if (tid < C) bs[tid] = b[tid];
    if (AFF) bn_coef(1, HID, gam_in, bet_in, N, sS, sT);
    __syncthreads();

    int n = blockIdx.x * 256 + tid;
    bool act = n < N;
    float acc[C];
#pragma unroll
    for (int j = 0; j < C; j++) acc[j] = 0.f;

    if (act) {
        float4 t0 = hin[(size_t)n * 4 + 0];
        float4 t1 = hin[(size_t)n * 4 + 1];
        float4 t2 = hin[(size_t)n * 4 + 2];
        float4 t3 = hin[(size_t)n * 4 + 3];

        int p   = g_rowptr[n];
        int end = g_woff[n];
        int deg = end - p;
        for (; p + 1 < end; p += 2) {
            int s0 = __ldg(g_adj + p);
            int s1 = __ldg(g_adj + p + 1);
            float4 a0 = hin[(size_t)s0 * 4 + 0], b0v = hin[(size_t)s1 * 4 + 0];
            float4 a1 = hin[(size_t)s0 * 4 + 1], b1v = hin[(size_t)s1 * 4 + 1];
            float4 a2 = hin[(size_t)s0 * 4 + 2], b2v = hin[(size_t)s1 * 4 + 2];
            float4 a3 = hin[(size_t)s0 * 4 + 3], b3v = hin[(size_t)s1 * 4 + 3];
            t0.x += a0.x + b0v.x; t0.y += a0.y + b0v.y; t0.z += a0.z + b0v.z; t0.w += a0.w + b0v.w;
            t1.x += a1.x + b1v.x; t1.y += a1.y + b1v.y; t1.z += a1.z + b1v.z; t1.w += a1.w + b1v.w;
            t2.x += a2.x + b2v.x; t2.y += a2.y + b2v.y; t2.z += a2.z + b2v.z; t2.w += a2.w + b2v.w;
            t3.x += a3.x + b3v.x; t3.y += a3.y + b3v.y; t3.z += a3.z + b3v.z; t3.w += a3.w + b3v.w;
        }
        if (p < end) {
            int s0 = __ldg(g_adj + p);
            float4 a0 = hin[(size_t)s0 * 4 + 0];
            float4 a1 = hin[(size_t)s0 * 4 + 1];
            float4 a2 = hin[(size_t)s0 * 4 + 2];
            float4 a3 = hin[(size_t)s0 * 4 + 3];
            t0.x += a0.x; t0.y += a0.y; t0.z += a0.z; t0.w += a0.w;
            t1.x += a1.x; t1.y += a1.y; t1.z += a1.z; t1.w += a1.w;
            t2.x += a2.x; t2.y += a2.y; t2.z += a2.z; t2.w += a2.w;
            t3.x += a3.x; t3.y += a3.y; t3.z += a3.z; t3.w += a3.w;
        }

        if (AFF) {   // Σ(s·pre+t) over (deg+1) nodes = s·Σpre + (deg+1)·t
            float dd = (float)(deg + 1);
            t0.x = sS[0]  * t0.x + dd * sT[0];  t0.y = sS[1]  * t0.y + dd * sT[1];
            t0.z = sS[2]  * t0.z + dd * sT[2];  t0.w = sS[3]  * t0.w + dd * sT[3];
            t1.x = sS[4]  * t1.x + dd * sT[4];  t1.y = sS[5]  * t1.y + dd * sT[5];
            t1.z = sS[6]  * t1.z + dd * sT[6];  t1.w = sS[7]  * t1.w + dd * sT[7];
            t2.x = sS[8]  * t2.x + dd * sT[8];  t2.y = sS[9]  * t2.y + dd * sT[9];
            t2.z = sS[10] * t2.z + dd * sT[10]; t2.w = sS[11] * t2.w + dd * sT[11];
            t3.x = sS[12] * t3.x + dd * sT[12]; t3.y = sS[13] * t3.y + dd * sT[13];
            t3.z = sS[14] * t3.z + dd * sT[14]; t3.w = sS[15] * t3.w + dd * sT[15];
        }

        float t[HID] = { t0.x, t0.y, t0.z, t0.w, t1.x, t1.y, t1.z, t1.w,
                         t2.x, t2.y, t2.z, t2.w, t3.x, t3.y, t3.z, t3.w };
#pragma unroll
        for (int j = 0; j < C; j++) acc[j] = bs[j];
#pragma unroll
        for (int k = 0; k < HID; k++) {
            float tv = t[k];
#pragma unroll
            for (int j = 0; j < C; j++) acc[j] += tv * Wsh[k * C + j];
        }
#pragma unroll
        for (int q = 0; q < C / 4; q++) {
            hout[(size_t)n * (C / 4) + q] =
                make_float4(acc[q*4+0], acc[q*4+1], acc[q*4+2], acc[q*4+3]);
        }
    }
    warp_stats<C>(acc, out_layer);
}

// ---------------- fused z0/z1/z2 (f32x2) + Z_sum + 3x segment_max ----------------
#define CHB 256
#define STR 260
#define ZTH 256
__global__ __launch_bounds__(ZTH) void k_bigz(const float* __restrict__ Wl0, const float* __restrict__ bl0,
                                              const float* __restrict__ Wl1, const float* __restrict__ bl1,
                                              const float* __restrict__ Wl2, const float* __restrict__ bl2,
                                              const float* __restrict__ gam1, const float* __restrict__ bet1,
                                              const int*   __restrict__ batch,
                                              float* __restrict__ Zs,
                                              int N, int DT, int NG) {
    __shared__ __align__(16) float sh[40 * STR];
    __shared__ int shb[CHB];
    __shared__ float s1c[HID], t1c[HID];
    int tid = threadIdx.x;
    bn_coef(1, HID, gam1, bet1, N, s1c, t1c);  // layer-1 affine applied on smem load
    __syncthreads();

    int j = blockIdx.y * ZTH + tid;
    bool fj = j < DT;

    unsigned long long W0p[HID], W1p[HID], W2p[HID2];
    unsigned long long bb0p = 0, bb1p = 0, bb2p = 0;
    if (fj) {
#pragma unroll
        for (int k = 0; k < HID; k++) {
            float w = Wl0[k * DT + j]; W0p[k] = pack2(w, w);
            float v = Wl1[k * DT + j]; W1p[k] = pack2(v, v);
        }
#pragma unroll
        for (int k = 0; k < HID2; k++) { float w = Wl2[k * DT + j]; W2p[k] = pack2(w, w); }
        float t0 = bl0[j], t1 = bl1[j], t2 = bl2[j];
        bb0p = pack2(t0, t0); bb1p = pack2(t1, t1); bb2p = pack2(t2, t2);
    }

    int n0 = blockIdx.x * CHB;
    int valid = N - n0; if (valid > CHB) valid = CHB;

    const float* h0f  = (const float*)g_h0;
    const float* pref = (const float*)g_pre;   // pre1 -> h1 on the fly
    const float* h2f  = (const float*)g_h2;
    for (int idx = tid; idx < valid * 16; idx += ZTH) {
        int n = idx >> 4, k = idx & 15;
        sh[k * STR + n]        = h0f[(size_t)(n0 + n) * 16 + k];
        float pv = pref[(size_t)(n0 + n) * 16 + k];
        sh[(16 + k) * STR + n] = s1c[k] * pv + t1c[k];
    }
    for (int idx = tid; idx < valid * 8; idx += ZTH) {
        int n = idx >> 3, k = idx & 7;
        sh[(32 + k) * STR + n] = h2f[(size_t)(n0 + n) * 8 + k];
    }
    if (tid < valid) shb[tid] = batch[n0 + tid];
    __syncthreads();
    if (!fj) return;

    const float NINF = __int_as_float(0xff800000);
    int cg = -1;
    float m0 = NINF, m1 = NINF, m2 = NINF;

    for (int nl = 0; nl < valid; nl += 4) {
        unsigned long long A0 = bb0p, B0 = bb0p;
        unsigned long long A1 = bb1p, B1 = bb1p;
        unsigned long long A2 = bb2p, B2 = bb2p;
#pragma unroll
        for (int k = 0; k < HID; k++) {
            ulonglong2 hv = *(const ulonglong2*)&sh[k * STR + nl];
            ffma2(A0, hv.x, W0p[k]); ffma2(B0, hv.y, W0p[k]);
        }
#pragma unroll
        for (int k = 0; k < HID; k++) {
            ulonglong2 hv = *(const ulonglong2*)&sh[(16 + k) * STR + nl];
            ffma2(A1, hv.x, W1p[k]); ffma2(B1, hv.y, W1p[k]);
        }
#pragma unroll
        for (int k = 0; k < HID2; k++) {
            ulonglong2 hv = *(const ulonglong2*)&sh[(32 + k) * STR + nl];
            ffma2(A2, hv.x, W2p[k]); ffma2(B2, hv.y, W2p[k]);
        }
        float a0[4], a1[4], a2[4];
        unpack2(A0, a0[0], a0[1]); unpack2(B0, a0[2], a0[3]);
        unpack2(A1, a1[0], a1[1]); unpack2(B1, a1[2], a1[3]);
        unpack2(A2, a2[0], a2[1]); unpack2(B2, a2[2], a2[3]);
#pragma unroll
        for (int i = 0; i < 4; i++) {
            if (nl + i >= valid) break;
            float z0 = gelu_exact(a0[i]);
            float z1 = a1[i], z2 = a2[i];
            if (Zs) __stcs(&Zs[(size_t)(n0 + nl + i) * DT + j], z0 + z1 + z2);
            int g = shb[nl + i];
            if (g != cg) {
                if ((unsigned)cg < (unsigned)NG) {
                    atomicMax(&g_pool[(size_t)cg * DT + j],            enc_f(m0));
                    atomicMax(&g_pool[((size_t)NG + cg) * DT + j],     enc_f(m1));
                    atomicMax(&g_pool[((size_t)2 * NG + cg) * DT + j], enc_f(m2));
                }
                cg = g; m0 = NINF; m1 = NINF; m2 = NINF;
            }
            m0 = fmaxf(m0, z0); m1 = fmaxf(m1, z1); m2 = fmaxf(m2, z2);
        }
    }
    if ((unsigned)cg < (unsigned)NG) {
        atomicMax(&g_pool[(size_t)cg * DT + j],            enc_f(m0));
        atomicMax(&g_pool[((size_t)NG + cg) * DT + j],     enc_f(m1));
        atomicMax(&g_pool[((size_t)2 * NG + cg) * DT + j], enc_f(m2));
    }
}

// ---------------- pooled output ----------------
__global__ void k_out(float* __restrict__ out, int DT, int NG) {
    int g = blockIdx.x;
    for (int j = threadIdx.x; j < DT; j += blockDim.x) {
        out[(size_t)g * DT + j] = dec_f(g_pool[(size_t)g * DT + j])
                                + dec_f(g_pool[((size_t)NG + g) * DT + j])
                                + dec_f(g_pool[((size_t)2 * NG + g) * DT + j]);
    }
}

// ---------------- launch ----------------
extern "C" void kernel_launch(void* const* d_in, const int* in_sizes, int n_in,
                              void* d_out, int out_size) {
    const float* x   = (const float*)d_in[0];
    const int*   ei  = (const int*)  d_in[1];
    const int*   bat = (const int*)  d_in[2];
    const float* W0  = (const float*)d_in[3];
    const float* b0  = (const float*)d_in[4];
    const float* g0  = (const float*)d_in[5];
    const float* be0 = (const float*)d_in[6];
    const float* Wl0 = (const float*)d_in[7];
    const float* bl0 = (const float*)d_in[8];
    const float* W1  = (const float*)d_in[9];
    const float* b1  = (const float*)d_in[10];
    const float* g1  = (const float*)d_in[11];
    const float* be1 = (const float*)d_in[12];
    const float* Wl1 = (const float*)d_in[13];
    const float* bl1 = (const float*)d_in[14];
    const float* W2  = (const float*)d_in[15];
    const float* b2  = (const float*)d_in[16];
    const float* g2  = (const float*)d_in[17];
    const float* be2 = (const float*)d_in[18];
    const float* Wl2 = (const float*)d_in[19];
    const float* bl2 = (const float*)d_in[20];

    const int F  = in_sizes[3] / HID;
    int       N  = (F > 0) ? in_sizes[0] / F : 0;
    int       E  = in_sizes[1] / 2;
    const int DT = in_sizes[7] / HID;
    if (N > N_MAX) N = N_MAX;
    if (E > E_MAX) E = E_MAX;

    long long rem = (long long)out_size - (long long)N * DT - (long long)N * 8;
    int NG; bool full_layout;
    if (DT > 0 && rem > 0 && rem % DT == 0 && rem / DT <= 65536) {
        NG = (int)(rem / DT); full_layout = true;
    } else {
        NG = (DT > 0) ? out_size / DT : 0; full_layout = false;
    }
    long long pool_n = 3LL * NG * DT;
    if (pool_n > POOL_CAP) pool_n = POOL_CAP;

    float*  out  = (float*)d_out;
    float*  outZ = 0;
    float4* outH = 0;
    if (full_layout) {
        outZ = out + (size_t)NG * DT;
        outH = (float4*)(outZ + (size_t)N * DT);
    }

    const int nb   = (N + 255) / 256;
    const int nb4  = (N * 4 + 255) / 256;
    const int nb2  = (N * 2 + 255) / 256;
    const int nbe  = (E + 255) / 256;
    const int nsb  = (N + SCAN_BS - 1) / SCAN_BS;

    const size_t smem0 = 256 * 36 * sizeof(float);   // 36,864 B

    long long init_n = pool_n > N ? pool_n : N;
    k_init<<<((int)init_n + 255) / 256, 256>>>((int)pool_n, N);

    // launch idx 3 = gemm0 (ncu window target)
    k_hist<<<nbe, 256>>>(ei, N, E);
    k_scan1<<<nsb, SCAN_BS>>>(N);
    k_gemm0<<<nb, 256, smem0>>>(x, W0, b0, N, F);
    k_scan2<<<1, 1024>>>(nsb);
    k_scan3<<<nsb, SCAN_BS>>>(N);
    k_fill<<<nbe, 256>>>(ei, N, E);
    k_bn0<<<nb4, 256>>>(g0, be0, N);

    // layer 1: h0 -> pre1 (g_pre), stats[1]
    k_gin<HID, false><<<nb, 256>>>(W1, b1, (const float*)0, (const float*)0, 1, N);
    // layer 2: pre1 (+analytic BN1) -> pre2 (g_h1, stride 2), stats[2]
    k_gin<HID2, true><<<nb, 256>>>(W2, b2, g1, be1, 2, N);
    // bn2: pre2 -> h2 (+ outH)
    k_bn2<<<nb2, 256>>>(g2, be2, outH, N);

    // fused projections + Z_sum + pools (h1 reconstructed from pre1 on the fly)
    dim3 gz((N + CHB - 1) / CHB, (DT + ZTH - 1) / ZTH);
    k_bigz<<<gz, ZTH>>>(Wl0, bl0, Wl1, bl1, Wl2, bl2, g1, be1, bat, outZ, N, DT, NG);
    k_out<<<NG, (DT < 1024 ? DT : 1024)>>>(out, DT, NG);
}

// round 17
// speedup vs baseline: 1.5856x; 1.0354x over previous
#include <cuda_runtime.h>
#include <math.h>

#define HID    16
#define HID2   8
#define BN_EPS 1e-5f

#define N_MAX   1048576
#define E_MAX   8388608
#define NB_MAX  4096
#define POOL_CAP (3 * 4194304)

// ---------------- scratch (device-side access only; never passed from host) ----------------
__device__ float4   g_pre [N_MAX * 4];   // pre1 (kept live through bigz)
__device__ float4   g_h0  [N_MAX * 4];
__device__ float4   g_h1  [N_MAX * 4];   // repurposed: pre2 (stride 2) after gin<8>
__device__ float4   g_h2  [N_MAX * 2];
__device__ int      g_cnt [N_MAX];
__device__ int      g_rowptr[N_MAX];
__device__ int      g_woff[N_MAX];
__device__ int      g_bsum[NB_MAX];
__device__ int      g_bpre[NB_MAX];
__device__ int      g_adj [E_MAX];
__device__ float    g_ssum[3][HID];
__device__ float    g_ssq [3][HID];
__device__ unsigned g_pool[POOL_CAP];

// ---------------- helpers ----------------
__device__ __forceinline__ float gelu_exact(float v) {
    return 0.5f * v * (1.0f + erff(v * 0.7071067811865476f));
}
__device__ __forceinline__ unsigned enc_f(float f) {
    unsigned u = __float_as_uint(f);
    return (u & 0x80000000u) ? ~u : (u | 0x80000000u);
}
__device__ __forceinline__ float dec_f(unsigned u) {
    return (u & 0x80000000u) ? __uint_as_float(u & 0x7FFFFFFFu)
                             : __uint_as_float(~u);
}
__device__ __forceinline__ unsigned long long pack2(float lo, float hi) {
    unsigned long long r;
    asm("mov.b64 %0, {%1, %2};" : "=l"(r) : "f"(lo), "f"(hi));
    return r;
}
__device__ __forceinline__ void unpack2(unsigned long long v, float& lo, float& hi) {
    asm("mov.b64 {%0, %1}, %2;" : "=f"(lo), "=f"(hi) : "l"(v));
}
__device__ __forceinline__ void ffma2(unsigned long long& d,
                                      unsigned long long a, unsigned long long b) {
    asm("fma.rn.f32x2 %0, %1, %2, %0;" : "+l"(d) : "l"(a), "l"(b));
}

__device__ __forceinline__ void bn_coef(int layer, int Cc, const float* gam,
                                        const float* bet, int N, float* sS, float* sT) {
    int tid = threadIdx.x;
    if (tid < Cc) {
        float inv = 1.0f / (float)N;
        float m   = g_ssum[layer][tid] * inv;
        float var = g_ssq[layer][tid] * inv - m * m;
        float sc  = gam[tid] * rsqrtf(var + BN_EPS);
        sS[tid] = sc;
        sT[tid] = bet[tid] - m * sc;
    }
}

template <int C>
__device__ __forceinline__ void warp_stats(const float* acc, int layer) {
#pragma unroll
    for (int j = 0; j < C; j++) {
        float v = acc[j];
        float q = v * v;
#pragma unroll
        for (int o = 16; o > 0; o >>= 1) {
            v += __shfl_xor_sync(0xffffffffu, v, o);
            q += __shfl_xor_sync(0xffffffffu, q, o);
        }
        if ((threadIdx.x & 31) == 0) {
            atomicAdd(&g_ssum[layer][j], v);
            atomicAdd(&g_ssq[layer][j],  q);
        }
    }
}

// ---------------- init ----------------
__global__ void k_init(int pool_n, int N) {
    int i = blockIdx.x * blockDim.x + threadIdx.x;
    if (i < 3 * HID) { ((float*)g_ssum)[i] = 0.f; ((float*)g_ssq)[i] = 0.f; }
    if (i < pool_n) g_pool[i] = 0u;
    if (i < N) g_cnt[i] = 0;
}

// ---------------- layer 0 GEMM (R9-proven): smem-staged x, fused stats ----------------
__global__ __launch_bounds__(256) void k_gemm0(const float* __restrict__ x,
                                               const float* __restrict__ W0,
                                               const float* __restrict__ b0,
                                               int N, int F) {
    extern __shared__ float xs[];          // [256][36]
    __shared__ float Wt[32 * HID];
    __shared__ float bs[HID];
    int tid = threadIdx.x;
    if (tid < HID) bs[tid] = b0[tid];

    int base = blockIdx.x * 256;
    int r = base + tid;
    bool act = r < N;

    unsigned long long accp[8];
#pragma unroll
    for (int q = 0; q < 8; q++) accp[q] = 0ull;

    int w  = tid >> 5;
    int l  = tid & 31;
    int lr = l >> 3;
    int lc = l & 7;
    int ntiles = F >> 5;

    for (int t = 0; t < ntiles; t++) {
        __syncthreads();
#pragma unroll
        for (int i = 0; i < 2; i++) {
            int idx = tid + i * 256;
            Wt[idx] = W0[(size_t)t * (32 * HID) + idx];
        }
#pragma unroll
        for (int k = 0; k < 8; k++) {
            int row_local = w * 32 + k * 4 + lr;
            int gr = base + row_local; if (gr >= N) gr = N - 1;
            float4 xv = __ldg((const float4*)(x + (size_t)gr * F + t * 32) + lc);
            *(float4*)&xs[row_local * 36 + lc * 4] = xv;
        }
        __syncthreads();
        const float* xr = &xs[tid * 36];
#pragma unroll
        for (int c4 = 0; c4 < 8; c4++) {
            float4 xv = *(const float4*)(xr + c4 * 4);
#pragma unroll
            for (int u = 0; u < 4; u++) {
                float xsc = (&xv.x)[u];
                unsigned long long xx = pack2(xsc, xsc);
                const ulonglong2* wr = (const ulonglong2*)&Wt[(c4 * 4 + u) * HID];
                ulonglong2 wa = wr[0], wb = wr[1];
                ffma2(accp[0], xx, wa.x); ffma2(accp[1], xx, wa.y);
                ffma2(accp[2], xx, wb.x); ffma2(accp[3], xx, wb.y);
                wa = wr[2]; wb = wr[3];
                ffma2(accp[4], xx, wa.x); ffma2(accp[5], xx, wa.y);
                ffma2(accp[6], xx, wb.x); ffma2(accp[7], xx, wb.y);
            }
        }
    }

    float acc[HID];
#pragma unroll
    for (int q = 0; q < 8; q++) unpack2(accp[q], acc[2 * q], acc[2 * q + 1]);
    if (act) {
#pragma unroll
        for (int j = 0; j < HID; j++) acc[j] += bs[j];
        float4* pr = (float4*)&g_pre[(size_t)r * 4];
        pr[0] = make_float4(acc[0],  acc[1],  acc[2],  acc[3]);
        pr[1] = make_float4(acc[4],  acc[5],  acc[6],  acc[7]);
        pr[2] = make_float4(acc[8],  acc[9],  acc[10], acc[11]);
        pr[3] = make_float4(acc[12], acc[13], acc[14], acc[15]);
    } else {
#pragma unroll
        for (int j = 0; j < HID; j++) acc[j] = 0.f;
    }
    warp_stats<HID>(acc, 0);
}

// ---------------- BN kernels: coalesced (thread per float4) ----------------
__global__ void k_bn0(const float* __restrict__ gam, const float* __restrict__ bet, int N) {
    __shared__ float sS[HID], sT[HID];
    bn_coef(0, HID, gam, bet, N, sS, sT);
    __syncthreads();
    int i = blockIdx.x * blockDim.x + threadIdx.x;
    if (i >= N * 4) return;
    int q = i & 3;
    float4 v = g_pre[i]; float4 r;
    r.x = gelu_exact(v.x * sS[q*4+0] + sT[q*4+0]);
    r.y = gelu_exact(v.y * sS[q*4+1] + sT[q*4+1]);
    r.z = gelu_exact(v.z * sS[q*4+2] + sT[q*4+2]);
    r.w = gelu_exact(v.w * sS[q*4+3] + sT[q*4+3]);
    g_h0[i] = r;
}

__global__ void k_bn2(const float* __restrict__ gam, const float* __restrict__ bet,
                      float4* __restrict__ outH, int N) {
    __shared__ float sS[HID2], sT[HID2];
    bn_coef(2, HID2, gam, bet, N, sS, sT);
    __syncthreads();
    int i = blockIdx.x * blockDim.x + threadIdx.x;
    if (i >= N * 2) return;
    int q = i & 1;
    float4 v = g_h1[i]; float4 r;       // pre2 lives in g_h1 (stride 2)
    r.x = v.x * sS[q*4+0] + sT[q*4+0];
    r.y = v.y * sS[q*4+1] + sT[q*4+1];
    r.z = v.z * sS[q*4+2] + sT[q*4+2];
    r.w = v.w * sS[q*4+3] + sT[q*4+3];
    g_h2[i] = r;
    if (outH) __stcs(&outH[i], r);
}

// ---------------- CSR build ----------------
__global__ void k_hist(const int* __restrict__ ei, int N, int E) {
    int e = blockIdx.x * blockDim.x + threadIdx.x;
    if (e >= E) return;
    int d = __ldg(ei + E + e);
    if ((unsigned)d < (unsigned)N) atomicAdd(&g_cnt[d], 1);
}

#define SCAN_BS 256
__global__ void k_scan1(int n) {
    __shared__ int sh[SCAN_BS];
    int i = blockIdx.x * SCAN_BS + threadIdx.x;
    int v = (i < n) ? g_cnt[i] : 0;
    sh[threadIdx.x] = v;
    __syncthreads();
#pragma unroll
    for (int o = 1; o < SCAN_BS; o <<= 1) {
        int t = (threadIdx.x >= o) ? sh[threadIdx.x - o] : 0;
        __syncthreads();
        sh[threadIdx.x] += t;
        __syncthreads();
    }
    if (i < n) g_rowptr[i] = sh[threadIdx.x] - v;
    if (threadIdx.x == SCAN_BS - 1) g_bsum[blockIdx.x] = sh[threadIdx.x];
}

__global__ void k_scan2(int nb) {
    __shared__ int sh[1024];
    __shared__ int carry;
    if (threadIdx.x == 0) carry = 0;
    __syncthreads();
    for (int base = 0; base < nb; base += 1024) {
        int i = base + threadIdx.x;
        int v = (i < nb) ? g_bsum[i] : 0;
        sh[threadIdx.x] = v;
        __syncthreads();
        for (int o = 1; o < 1024; o <<= 1) {
            int t = (threadIdx.x >= o) ? sh[threadIdx.x - o] : 0;
            __syncthreads();
            sh[threadIdx.x] += t;
            __syncthreads();
        }
        if (i < nb) g_bpre[i] = sh[threadIdx.x] - v + carry;
        __syncthreads();
        if (threadIdx.x == 1023) carry += sh[1023];
        __syncthreads();
    }
}

__global__ void k_scan3(int n) {
    int i = blockIdx.x * SCAN_BS + threadIdx.x;
    if (i >= n) return;
    int v = g_rowptr[i] + g_bpre[blockIdx.x];
    g_rowptr[i] = v;
    g_woff[i]   = v;
}

__global__ void k_fill(const int* __restrict__ ei, int N, int E) {
    int e = blockIdx.x * blockDim.x + threadIdx.x;
    if (e >= E) return;
    int s = __ldg(ei + e);
    int d = __ldg(ei + E + e);
    if ((unsigned)s >= (unsigned)N || (unsigned)d >= (unsigned)N) return;
    int pos = atomicAdd(&g_woff[d], 1);
    if (pos < E_MAX) g_adj[pos] = s;
}

// ---------------- GIN (per-thread, R9-proven gather) + optional analytic BN1 ----------------
// AFF=false: in=g_h0 (h0),           out=g_pre (stride 4, pre1), stats layer 1
// AFF=true : in=g_pre (pre1+affine), out=g_h1  (stride 2, pre2), stats layer 2
template <int C, bool AFF>
__global__ __launch_bounds__(256) void k_gin(const float* __restrict__ W,
                                             const float* __restrict__ b,
                                             const float* __restrict__ gam_in,
                                             const float* __restrict__ bet_in,
                                             int out_layer, int N) {
    const float4* hin  = AFF ? g_pre : g_h0;   // device-side selection ONLY
    float4*       hout = AFF ? g_h1  : g_pre;

    __shared__ float Wsh[HID * C];
    __shared__ float bs[C];
    __shared__ float sS[HID], sT[HID];
    int tid = threadIdx.x;
    for (int i = tid; i < HID * C; i += 256) Wsh[i] = W[i];
    if (tid < C) bs[tid] = b[tid];
    if (AFF) bn_coef(1, HID, gam_in, bet_in, N, sS, sT);
    __syncthreads();

    int n = blockIdx.x * 256 + tid;
    bool act = n < N;
    float acc[C];
#pragma unroll
    for (int j = 0; j < C; j++) acc[j] = 0.f;

    if (act) {
        float4 t0 = hin[(size_t)n * 4 + 0];
        float4 t1 = hin[(size_t)n * 4 + 1];
        float4 t2 = hin[(size_t)n * 4 + 2];
        float4 t3 = hin[(size_t)n * 4 + 3];

        int p   = g_rowptr[n];
        int end = g_woff[n];
        int deg = end - p;
        for (; p + 1 < end; p += 2) {
            int s0 = __ldg(g_adj + p);
            int s1 = __ldg(g_adj + p + 1);
            float4 a0 = hin[(size_t)s0 * 4 + 0], b0v = hin[(size_t)s1 * 4 + 0];
            float4 a1 = hin[(size_t)s0 * 4 + 1], b1v = hin[(size_t)s1 * 4 + 1];
            float4 a2 = hin[(size_t)s0 * 4 + 2], b2v = hin[(size_t)s1 * 4 + 2];
            float4 a3 = hin[(size_t)s0 * 4 + 3], b3v = hin[(size_t)s1 * 4 + 3];
            t0.x += a0.x + b0v.x; t0.y += a0.y + b0v.y; t0.z += a0.z + b0v.z; t0.w += a0.w + b0v.w;
            t1.x += a1.x + b1v.x; t1.y += a1.y + b1v.y; t1.z += a1.z + b1v.z; t1.w += a1.w + b1v.w;
            t2.x += a2.x + b2v.x; t2.y += a2.y + b2v.y; t2.z += a2.z + b2v.z; t2.w += a2.w + b2v.w;
            t3.x += a3.x + b3v.x; t3.y += a3.y + b3v.y; t3.z += a3.z + b3v.z; t3.w += a3.w + b3v.w;
        }
        if (p < end) {
            int s0 = __ldg(g_adj + p);
            float4 a0 = hin[(size_t)s0 * 4 + 0];
            float4 a1 = hin[(size_t)s0 * 4 + 1];
            float4 a2 = hin[(size_t)s0 * 4 + 2];
            float4 a3 = hin[(size_t)s0 * 4 + 3];
            t0.x += a0.x; t0.y += a0.y; t0.z += a0.z; t0.w += a0.w;
            t1.x += a1.x; t1.y += a1.y; t1.z += a1.z; t1.w += a1.w;
            t2.x += a2.x; t2.y += a2.y; t2.z += a2.z; t2.w += a2.w;
            t3.x += a3.x; t3.y += a3.y; t3.z += a3.z; t3.w += a3.w;
        }

        if (AFF) {   // Σ(s·pre+t) over (deg+1) nodes = s·Σpre + (deg+1)·t
            float dd = (float)(deg + 1);
            t0.x = sS[0]  * t0.x + dd * sT[0];  t0.y = sS[1]  * t0.y + dd * sT[1];
            t0.z = sS[2]  * t0.z + dd * sT[2];  t0.w = sS[3]  * t0.w + dd * sT[3];
            t1.x = sS[4]  * t1.x + dd * sT[4];  t1.y = sS[5]  * t1.y + dd * sT[5];
            t1.z = sS[6]  * t1.z + dd * sT[6];  t1.w = sS[7]  * t1.w + dd * sT[7];
            t2.x = sS[8]  * t2.x + dd * sT[8];  t2.y = sS[9]  * t2.y + dd * sT[9];
            t2.z = sS[10] * t2.z + dd * sT[10]; t2.w = sS[11] * t2.w + dd * sT[11];
            t3.x = sS[12] * t3.x + dd * sT[12]; t3.y = sS[13] * t3.y + dd * sT[13];
            t3.z = sS[14] * t3.z + dd * sT[14]; t3.w = sS[15] * t3.w + dd * sT[15];
        }

        float t[HID] = { t0.x, t0.y, t0.z, t0.w, t1.x, t1.y, t1.z, t1.w,
                         t2.x, t2.y, t2.z, t2.w, t3.x, t3.y, t3.z, t3.w };
#pragma unroll
        for (int j = 0; j < C; j++) acc[j] = bs[j];
#pragma unroll
        for (int k = 0; k < HID; k++) {
            float tv = t[k];
#pragma unroll
            for (int j = 0; j < C; j++) acc[j] += tv * Wsh[k * C + j];
        }
#pragma unroll
        for (int q = 0; q < C / 4; q++) {
            hout[(size_t)n * (C / 4) + q] =
                make_float4(acc[q*4+0], acc[q*4+1], acc[q*4+2], acc[q*4+3]);
        }
    }
    warp_stats<C>(acc, out_layer);
}

// ---------------- fused z0/z1/z2 (f32x2) + Z_sum + 3x segment_max ----------------
// Tile staged ONCE per 256-node chunk; per-block loop covers all DT features.
#define CHB 256
#define STR 260
#define ZTH 256
__global__ __launch_bounds__(ZTH) void k_bigz(const float* __restrict__ Wl0, const float* __restrict__ bl0,
                                              const float* __restrict__ Wl1, const float* __restrict__ bl1,
                                              const float* __restrict__ Wl2, const float* __restrict__ bl2,
                                              const float* __restrict__ gam1, const float* __restrict__ bet1,
                                              const int*   __restrict__ batch,
                                              float* __restrict__ Zs,
                                              int N, int DT, int NG) {
    __shared__ __align__(16) float sh[40 * STR];
    __shared__ int shb[CHB];
    __shared__ float s1c[HID], t1c[HID];
    int tid = threadIdx.x;
    bn_coef(1, HID, gam1, bet1, N, s1c, t1c);  // layer-1 affine applied on smem load
    __syncthreads();

    int n0 = blockIdx.x * CHB;
    int valid = N - n0; if (valid > CHB) valid = CHB;

    const float* h0f  = (const float*)g_h0;
    const float* pref = (const float*)g_pre;   // pre1 -> h1 on the fly
    const float* h2f  = (const float*)g_h2;
    for (int idx = tid; idx < valid * 16; idx += ZTH) {
        int n = idx >> 4, k = idx & 15;
        sh[k * STR + n]        = h0f[(size_t)(n0 + n) * 16 + k];
        float pv = pref[(size_t)(n0 + n) * 16 + k];
        sh[(16 + k) * STR + n] = s1c[k] * pv + t1c[k];
    }
    for (int idx = tid; idx < valid * 8; idx += ZTH) {
        int n = idx >> 3, k = idx & 7;
        sh[(32 + k) * STR + n] = h2f[(size_t)(n0 + n) * 8 + k];
    }
    if (tid < valid) shb[tid] = batch[n0 + tid];
    __syncthreads();

    const float NINF = __int_as_float(0xff800000);

    // loop over feature halves: stage-once, compute-many
    for (int j0 = 0; j0 < DT; j0 += ZTH) {
        int j = j0 + tid;
        if (j >= DT) break;   // uniform across block when DT % ZTH == 0; safe otherwise per-thread

        unsigned long long W0p[HID], W1p[HID], W2p[HID2];
#pragma unroll
        for (int k = 0; k < HID; k++) {
            float w = Wl0[k * DT + j]; W0p[k] = pack2(w, w);
            float v = Wl1[k * DT + j]; W1p[k] = pack2(v, v);
        }
#pragma unroll
        for (int k = 0; k < HID2; k++) { float w = Wl2[k * DT + j]; W2p[k] = pack2(w, w); }
        float tb0 = bl0[j], tb1 = bl1[j], tb2 = bl2[j];
        unsigned long long bb0p = pack2(tb0, tb0);
        unsigned long long bb1p = pack2(tb1, tb1);
        unsigned long long bb2p = pack2(tb2, tb2);

        int cg = -1;
        float m0 = NINF, m1 = NINF, m2 = NINF;

        for (int nl = 0; nl < valid; nl += 4) {
            unsigned long long A0 = bb0p, B0 = bb0p;
            unsigned long long A1 = bb1p, B1 = bb1p;
            unsigned long long A2 = bb2p, B2 = bb2p;
#pragma unroll
            for (int k = 0; k < HID; k++) {
                ulonglong2 hv = *(const ulonglong2*)&sh[k * STR + nl];
                ffma2(A0, hv.x, W0p[k]); ffma2(B0, hv.y, W0p[k]);
            }
#pragma unroll
            for (int k = 0; k < HID; k++) {
                ulonglong2 hv = *(const ulonglong2*)&sh[(16 + k) * STR + nl];
                ffma2(A1, hv.x, W1p[k]); ffma2(B1, hv.y, W1p[k]);
            }
#pragma unroll
            for (int k = 0; k < HID2; k++) {
                ulonglong2 hv = *(const ulonglong2*)&sh[(32 + k) * STR + nl];
                ffma2(A2, hv.x, W2p[k]); ffma2(B2, hv.y, W2p[k]);
            }
            float a0[4], a1[4], a2[4];
            unpack2(A0, a0[0], a0[1]); unpack2(B0, a0[2], a0[3]);
            unpack2(A1, a1[0], a1[1]); unpack2(B1, a1[2], a1[3]);
            unpack2(A2, a2[0], a2[1]); unpack2(B2, a2[2], a2[3]);
#pragma unroll
            for (int i = 0; i < 4; i++) {
                if (nl + i >= valid) break;
                float z0 = gelu_exact(a0[i]);
                float z1 = a1[i], z2 = a2[i];
                if (Zs) __stcs(&Zs[(size_t)(n0 + nl + i) * DT + j], z0 + z1 + z2);
                int g = shb[nl + i];
                if (g != cg) {
                    if ((unsigned)cg < (unsigned)NG) {
                        atomicMax(&g_pool[(size_t)cg * DT + j],            enc_f(m0));
                        atomicMax(&g_pool[((size_t)NG + cg) * DT + j],     enc_f(m1));
                        atomicMax(&g_pool[((size_t)2 * NG + cg) * DT + j], enc_f(m2));
                    }
                    cg = g; m0 = NINF; m1 = NINF; m2 = NINF;
                }
                m0 = fmaxf(m0, z0); m1 = fmaxf(m1, z1); m2 = fmaxf(m2, z2);
            }
        }
        if ((unsigned)cg < (unsigned)NG) {
            atomicMax(&g_pool[(size_t)cg * DT + j],            enc_f(m0));
            atomicMax(&g_pool[((size_t)NG + cg) * DT + j],     enc_f(m1));
            atomicMax(&g_pool[((size_t)2 * NG + cg) * DT + j], enc_f(m2));
        }
    }
}

// ---------------- pooled output ----------------
__global__ void k_out(float* __restrict__ out, int DT, int NG) {
    int g = blockIdx.x;
    for (int j = threadIdx.x; j < DT; j += blockDim.x) {
        out[(size_t)g * DT + j] = dec_f(g_pool[(size_t)g * DT + j])
                                + dec_f(g_pool[((size_t)NG + g) * DT + j])
                                + dec_f(g_pool[((size_t)2 * NG + g) * DT + j]);
    }
}

// ---------------- launch ----------------
extern "C" void kernel_launch(void* const* d_in, const int* in_sizes, int n_in,
                              void* d_out, int out_size) {
    const float* x   = (const float*)d_in[0];
    const int*   ei  = (const int*)  d_in[1];
    const int*   bat = (const int*)  d_in[2];
    const float* W0  = (const float*)d_in[3];
    const float* b0  = (const float*)d_in[4];
    const float* g0  = (const float*)d_in[5];
    const float* be0 = (const float*)d_in[6];
    const float* Wl0 = (const float*)d_in[7];
    const float* bl0 = (const float*)d_in[8];
    const float* W1  = (const float*)d_in[9];
    const float* b1  = (const float*)d_in[10];
    const float* g1  = (const float*)d_in[11];
    const float* be1 = (const float*)d_in[12];
    const float* Wl1 = (const float*)d_in[13];
    const float* bl1 = (const float*)d_in[14];
    const float* W2  = (const float*)d_in[15];
    const float* b2  = (const float*)d_in[16];
    const float* g2  = (const float*)d_in[17];
    const float* be2 = (const float*)d_in[18];
    const float* Wl2 = (const float*)d_in[19];
    const float* bl2 = (const float*)d_in[20];

    const int F  = in_sizes[3] / HID;
    int       N  = (F > 0) ? in_sizes[0] / F : 0;
    int       E  = in_sizes[1] / 2;
    const int DT = in_sizes[7] / HID;
    if (N > N_MAX) N = N_MAX;
    if (E > E_MAX) E = E_MAX;

    long long rem = (long long)out_size - (long long)N * DT - (long long)N * 8;
    int NG; bool full_layout;
    if (DT > 0 && rem > 0 && rem % DT == 0 && rem / DT <= 65536) {
        NG = (int)(rem / DT); full_layout = true;
    } else {
        NG = (DT > 0) ? out_size / DT : 0; full_layout = false;
    }
    long long pool_n = 3LL * NG * DT;
    if (pool_n > POOL_CAP) pool_n = POOL_CAP;

    float*  out  = (float*)d_out;
    float*  outZ = 0;
    float4* outH = 0;
    if (full_layout) {
        outZ = out + (size_t)NG * DT;
        outH = (float4*)(outZ + (size_t)N * DT);
    }

    const int nb   = (N + 255) / 256;
    const int nb4  = (N * 4 + 255) / 256;
    const int nb2  = (N * 2 + 255) / 256;
    const int nbe  = (E + 255) / 256;
    const int nsb  = (N + SCAN_BS - 1) / SCAN_BS;

    const size_t smem0 = 256 * 36 * sizeof(float);   // 36,864 B

    long long init_n = pool_n > N ? pool_n : N;
    k_init<<<((int)init_n + 255) / 256, 256>>>((int)pool_n, N);

    // launch idx 3 = gemm0 (ncu window target)
    k_hist<<<nbe, 256>>>(ei, N, E);
    k_scan1<<<nsb, SCAN_BS>>>(N);
    k_gemm0<<<nb, 256, smem0>>>(x, W0, b0, N, F);
    k_scan2<<<1, 1024>>>(nsb);
    k_scan3<<<nsb, SCAN_BS>>>(N);
    k_fill<<<nbe, 256>>>(ei, N, E);
    k_bn0<<<nb4, 256>>>(g0, be0, N);

    // layer 1: h0 -> pre1 (g_pre), stats[1]
    k_gin<HID, false><<<nb, 256>>>(W1, b1, (const float*)0, (const float*)0, 1, N);
    // layer 2: pre1 (+analytic BN1) -> pre2 (g_h1, stride 2), stats[2]
    k_gin<HID2, true><<<nb, 256>>>(W2, b2, g1, be1, 2, N);
    // bn2: pre2 -> h2 (+ outH)
    k_bn2<<<nb2, 256>>>(g2, be2, outH, N);

    // fused projections + Z_sum + pools (tile staged once, j-loop inside)
    k_bigz<<<(N + CHB - 1) / CHB, ZTH>>>(Wl0, bl0, Wl1, bl1, Wl2, bl2, g1, be1, bat, outZ, N, DT, NG);
    k_out<<<NG, (DT < 1024 ? DT : 1024)>>>(out, DT, NG);
}